// round 8
// baseline (speedup 1.0000x reference)
#include <cuda_runtime.h>
#include <cuda_fp16.h>
#include <cstdint>
#include <cmath>

#define CDIM 512
#define NDIM 512
#define BDIM 64
#define TT 4
#define BP 16           // BDIM / TT
#define HH 8
#define GDIM 64
#define EPSF 1e-5f
#define CN (CDIM*NDIM)  // 262144
#define MTOT_QKV 1536

// qkv fused kernel smem: stage = A0(16K)+A1(16K)+B0(16K)+B1(16K) = 64KB
#define QBUF 65536
#define QSMEM (2*QBUF + 65536)    // + 64KB membrane state = 196608

// proj kernel smem (256-wide B)
#define PBUF 98304
#define PSMEM (2*PBUF)

// attn fused smem: kb(4K)+vb(4K)+Ms(16K)+qs(8K)+mem[64][128](32K) = 64KB
#define ASMEM 65536

// ---------------------------------------------------------------------------
// Scratch (device globals: allocation-free per harness rules)
// ---------------------------------------------------------------------------
__device__ __half        g_w2  [2ull*MTOT_QKV*CDIM];          // qkv weight splits
__device__ __half        g_wp2 [2ull*CDIM*CDIM];              // proj weight splits
__device__ __half        g_xt2 [2ull*BDIM*CN];                // x splits, [s][b][n][c]
__device__ unsigned char g_spk [3ull*BDIM*CN];                // qkv spikes [w][b][c][n]
__device__ __half        g_st  [(unsigned long long)BDIM*CN]; // final spikes fp16 [b][n][c]

// ---------------------------------------------------------------------------
// PTX helpers (baseline sm_80+, valid on compute_103 target)
// ---------------------------------------------------------------------------
__device__ __forceinline__ uint32_t smem_u32(const void* p) {
    uint32_t a;
    asm("{ .reg .u64 t; cvta.to.shared.u64 t, %1; cvt.u32.u64 %0, t; }" : "=r"(a) : "l"(p));
    return a;
}
#define LDSM4(r0,r1,r2,r3,addr) \
    asm volatile("ldmatrix.sync.aligned.m8n8.x4.shared.b16 {%0,%1,%2,%3}, [%4];" \
        : "=r"(r0),"=r"(r1),"=r"(r2),"=r"(r3) : "r"(addr))

__device__ __forceinline__ void mma16816(float* c, const uint32_t* a,
                                         uint32_t b0, uint32_t b1) {
    asm volatile("mma.sync.aligned.m16n8k16.row.col.f32.f16.f16.f32 "
        "{%0,%1,%2,%3}, {%4,%5,%6,%7}, {%8,%9}, {%0,%1,%2,%3};"
        : "+f"(c[0]), "+f"(c[1]), "+f"(c[2]), "+f"(c[3])
        : "r"(a[0]), "r"(a[1]), "r"(a[2]), "r"(a[3]), "r"(b0), "r"(b1));
}
__device__ __forceinline__ void cp_async16(uint32_t dst, const void* src) {
    asm volatile("cp.async.cg.shared.global [%0], [%1], 16;" :: "r"(dst), "l"(src));
}
__device__ __forceinline__ uint32_t swz(uint32_t bo) {
    return bo ^ (((bo >> 7) & 7u) << 4);
}

// ---------------------------------------------------------------------------
// Weight splits: w -> (fp16 hi, fp16 residual)
// ---------------------------------------------------------------------------
__global__ void wsplit_kernel(const float* __restrict__ wq, const float* __restrict__ wk,
                              const float* __restrict__ wv, const float* __restrict__ wp)
{
    int i = blockIdx.x * 256 + threadIdx.x;
    if (i < MTOT_QKV * CDIM) {
        int o = i >> 9;
        const float* src = (o < 512) ? wq : (o < 1024 ? wk : wv);
        float v = src[((o & 511) << 9) | (i & 511)];
        __half h0 = __float2half_rn(v);
        float r1 = v - __half2float(h0);
        g_w2[i] = h0;
        g_w2[(size_t)MTOT_QKV * CDIM + i] = __float2half_rn(r1);
    }
    if (i < CDIM * CDIM) {
        float v = wp[i];
        __half h0 = __float2half_rn(v);
        float r1 = v - __half2float(h0);
        g_wp2[i] = h0;
        g_wp2[(size_t)CDIM * CDIM + i] = __float2half_rn(r1);
    }
}

// ---------------------------------------------------------------------------
// x split + transpose: x[b][c][n] fp32 -> g_xt2[s][b][n][c] fp16 (2 splits)
// ---------------------------------------------------------------------------
__global__ void xsplit_kernel(const float* __restrict__ x)
{
    __shared__ float tile[32][33];
    const int b = blockIdx.z, c0 = blockIdx.y * 32, n0 = blockIdx.x * 32;
    const float* xb = x + (size_t)b * CN;
    const int tx = threadIdx.x, ty = threadIdx.y;   // 32 x 8
    #pragma unroll
    for (int r = 0; r < 4; ++r) {
        int cl = ty * 4 + r;
        tile[cl][tx] = xb[(size_t)(c0 + cl) * NDIM + n0 + tx];
    }
    __syncthreads();
    const size_t SEG = (size_t)BDIM * CN;
    #pragma unroll
    for (int r = 0; r < 4; ++r) {
        int nl = ty * 4 + r, cl = tx;
        float v = tile[cl][nl];
        __half h0 = __float2half_rn(v);
        float r1 = v - __half2float(h0);
        size_t o = ((size_t)b * NDIM + (n0 + nl)) * CDIM + c0 + cl;
        g_xt2[o] = h0;
        g_xt2[SEG + o] = __float2half_rn(r1);
    }
}

// ---------------------------------------------------------------------------
// Fused QKV: split-HMMA GEMM + BN + LIF scan over T, spikes out (u8).
// CTA: 128(M) x 128(N), grid.z = b' (16); inner loop t=0..3, b = t*16+b'.
// ---------------------------------------------------------------------------
__device__ __forceinline__ void qkv_load_chunk(
    const __half* __restrict__ A0, const __half* __restrict__ A1,
    const __half* __restrict__ B0, const __half* __restrict__ B1,
    int mBase, int n0g, int kOff, uint32_t buf, int tid)
{
    #pragma unroll
    for (int it = 0; it < 16; ++it) {
        int i = tid + it * 256;          // 0..4095
        int s = i & 7;
        int r = (i >> 3) & 127;
        int seg = i >> 10;               // 0:A0 1:A1 2:B0 3:B1
        const __half* g;
        if (seg == 0)      g = A0 + (size_t)(mBase + r) * CDIM + kOff + s * 8;
        else if (seg == 1) g = A1 + (size_t)(mBase + r) * CDIM + kOff + s * 8;
        else if (seg == 2) g = B0 + (size_t)(n0g  + r) * CDIM + kOff + s * 8;
        else               g = B1 + (size_t)(n0g  + r) * CDIM + kOff + s * 8;
        cp_async16(buf + (uint32_t)(seg << 14) + swz((uint32_t)(r * 128 + s * 16)), g);
    }
}

__global__ void __launch_bounds__(256, 1)
qkv_gemm_lif(const __half* __restrict__ A0g, const __half* __restrict__ A1g,
             const __half* __restrict__ B0base, const __half* __restrict__ B1base,
             unsigned char* __restrict__ spk,
             const float* __restrict__ bg, const float* __restrict__ bb,
             const float* __restrict__ bm, const float* __restrict__ bv)
{
    extern __shared__ __align__(128) unsigned char dsm[];
    const uint32_t sbase = smem_u32(dsm);
    float* memS = (float*)(dsm + 2 * QBUF);

    const int tid = threadIdx.x, lane = tid & 31, wid = tid >> 5;
    const int warpM = wid >> 2, warpN = wid & 3;       // 2 x 4 warps, 64x32 each
    const int bz    = blockIdx.z;                      // b' 0..15
    const int mBase = blockIdx.y * 128;
    const int n0g   = blockIdx.x * 128;

    float invR[4][2], biasR[4][2];
    size_t rowB[4][2];
    #pragma unroll
    for (int mt = 0; mt < 4; ++mt)
        #pragma unroll
        for (int hf = 0; hf < 2; ++hf) {
            int o = mBase + warpM * 64 + mt * 16 + (lane >> 2) + hf * 8;
            int w = o >> 9, c = o & 511;
            float inv = bg[w * CDIM + c] / sqrtf(bv[w * CDIM + c] + EPSF);
            invR[mt][hf]  = inv;
            biasR[mt][hf] = bb[w * CDIM + c] - bm[w * CDIM + c] * inv;
            rowB[mt][hf]  = (size_t)w * BDIM * CN + (size_t)c * NDIM;
        }

    #pragma unroll
    for (int idx = 0; idx < 64; ++idx) memS[idx * 256 + tid] = 0.f;

    float acc[4][4][4];
    #pragma unroll
    for (int i = 0; i < 4; ++i)
        #pragma unroll
        for (int j = 0; j < 4; ++j)
            #pragma unroll
            for (int k = 0; k < 4; ++k) acc[i][j][k] = 0.f;

    #pragma unroll 1
    for (int t = 0; t < TT; ++t) {
        const int b = t * BP + bz;
        const __half* B0 = B0base + (size_t)b * CN;
        const __half* B1 = B1base + (size_t)b * CN;

        qkv_load_chunk(A0g, A1g, B0, B1, mBase, n0g, 0, sbase, tid);
        asm volatile("cp.async.commit_group;");

        int buf = 0;
        #pragma unroll 1
        for (int c = 0; c < 8; ++c) {
            if (c < 7) {
                qkv_load_chunk(A0g, A1g, B0, B1, mBase, n0g, (c + 1) * 64,
                               sbase + (buf ^ 1) * QBUF, tid);
                asm volatile("cp.async.commit_group;");
                asm volatile("cp.async.wait_group 1;");
            } else {
                asm volatile("cp.async.wait_group 0;");
            }
            __syncthreads();

            const uint32_t base = sbase + buf * QBUF;
            #pragma unroll
            for (int ks = 0; ks < 4; ++ks) {
                uint32_t a0[4][4], a1[4][4];
                const int khA = ks * 16 + (lane >> 4) * 8;
                #pragma unroll
                for (int mt = 0; mt < 4; ++mt) {
                    int row = warpM * 64 + mt * 16 + (lane & 7) + ((lane >> 3) & 1) * 8;
                    uint32_t bo = swz((uint32_t)(row * 128 + khA * 2));
                    LDSM4(a0[mt][0], a0[mt][1], a0[mt][2], a0[mt][3], base + bo);
                    LDSM4(a1[mt][0], a1[mt][1], a1[mt][2], a1[mt][3], base + 16384u + bo);
                }
                const int khB = ks * 16 + ((lane >> 3) & 1) * 8;
                #pragma unroll
                for (int nt2 = 0; nt2 < 2; ++nt2) {
                    int nrow = warpN * 32 + nt2 * 16 + (lane & 7) + ((lane >> 4) & 1) * 8;
                    uint32_t bo = swz((uint32_t)(nrow * 128 + khB * 2));
                    uint32_t rb[4];
                    LDSM4(rb[0], rb[1], rb[2], rb[3], base + 32768u + bo);
                    #pragma unroll
                    for (int mt = 0; mt < 4; ++mt) {
                        mma16816(acc[mt][nt2*2+0], a0[mt], rb[0], rb[1]);
                        mma16816(acc[mt][nt2*2+1], a0[mt], rb[2], rb[3]);
                        mma16816(acc[mt][nt2*2+0], a1[mt], rb[0], rb[1]);
                        mma16816(acc[mt][nt2*2+1], a1[mt], rb[2], rb[3]);
                    }
                    LDSM4(rb[0], rb[1], rb[2], rb[3], base + 49152u + bo);
                    #pragma unroll
                    for (int mt = 0; mt < 4; ++mt) {
                        mma16816(acc[mt][nt2*2+0], a0[mt], rb[0], rb[1]);
                        mma16816(acc[mt][nt2*2+1], a0[mt], rb[2], rb[3]);
                    }
                }
            }
            __syncthreads();
            buf ^= 1;
        }

        // epilogue: BN + LIF step + spike write (per-thread-exclusive memS)
        #pragma unroll
        for (int mt = 0; mt < 4; ++mt)
            #pragma unroll
            for (int hf = 0; hf < 2; ++hf) {
                const float inv = invR[mt][hf], bias = biasR[mt][hf];
                unsigned char* ucRow = spk + rowB[mt][hf] + (size_t)b * CN;
                #pragma unroll
                for (int nt = 0; nt < 4; ++nt) {
                    int idx = mt * 16 + nt * 4 + hf * 2;
                    int nn  = n0g + warpN * 32 + nt * 8 + (lane & 3) * 2;
                    float pre0 = acc[mt][nt][hf*2+0] * inv + bias;
                    float pre1 = acc[mt][nt][hf*2+1] * inv + bias;
                    float m0 = memS[(idx+0) * 256 + tid] * 0.5f + pre0;
                    float m1 = memS[(idx+1) * 256 + tid] * 0.5f + pre1;
                    uchar2 s;
                    s.x = m0 > 1.0f; if (s.x) m0 = 0.f;
                    s.y = m1 > 1.0f; if (s.y) m1 = 0.f;
                    memS[(idx+0) * 256 + tid] = m0;
                    memS[(idx+1) * 256 + tid] = m1;
                    *(uchar2*)(ucRow + nn) = s;
                    acc[mt][nt][hf*2+0] = 0.f;
                    acc[mt][nt][hf*2+1] = 0.f;
                }
            }
    }
}

// ---------------------------------------------------------------------------
// Fused attention + LIF, n-chunked for occupancy.
// Grid (4 nchunks, HH, BP).  Each CTA: t-loop, full k/v bitpack + popcount M,
// q*M on its 128-n slab, LIF with mem[64][128] in smem, fp16 spikes out
// in proj-ready [b][n][c] layout.
// ---------------------------------------------------------------------------
__global__ void __launch_bounds__(256)
attn_lif(const unsigned char* __restrict__ spk, __half* __restrict__ st)
{
    extern __shared__ __align__(128) unsigned char dsm[];
    unsigned int (*kb)[16]   = (unsigned int (*)[16])(dsm);
    unsigned int (*vb)[16]   = (unsigned int (*)[16])(dsm + 4096);
    float (*Ms)[64]          = (float (*)[64])(dsm + 8192);
    unsigned char (*qs)[128] = (unsigned char (*)[128])(dsm + 24576);
    float* memS              = (float*)(dsm + 32768);   // [64][128]

    const int nb = blockIdx.x * 128;     // n-chunk base
    const int h  = blockIdx.y;
    const int bp = blockIdx.z;           // b' 0..15
    const int tid  = threadIdx.x;
    const int lane = tid & 31;
    const int warp = tid >> 5;

    const int nLocal = tid & 127;        // n within chunk
    const int d0     = (tid >> 7) * 32;  // 0 or 32

    // zero membrane (per-thread exclusive cells)
    #pragma unroll
    for (int j = 0; j < 32; ++j) memS[(d0 + j) * 128 + nLocal] = 0.f;

    #pragma unroll 1
    for (int t = 0; t < TT; ++t) {
        const int b = t * BP + bp;
        const size_t head_off = ((size_t)b * CDIM + (size_t)h * GDIM) * NDIM;
        const unsigned char* qS = spk + 0ull * BDIM * CN + head_off;
        const unsigned char* kS = spk + 1ull * BDIM * CN + head_off;
        const unsigned char* vS = spk + 2ull * BDIM * CN + head_off;

        __syncthreads();   // protect kb/vb/qs from previous iteration readers

        // bitpack k and v rows via ballot (full 512-m range)
        #pragma unroll
        for (int r = 0; r < 8; ++r) {
            int e = warp * 8 + r;
            #pragma unroll
            for (int w = 0; w < 16; ++w) {
                unsigned int bkk = __ballot_sync(0xffffffffu, kS[(size_t)e * NDIM + w * 32 + lane] != 0);
                unsigned int bvv = __ballot_sync(0xffffffffu, vS[(size_t)e * NDIM + w * 32 + lane] != 0);
                if (lane == 0) { kb[e][w] = bkk; vb[e][w] = bvv; }
            }
        }
        // stage q slab (64 rows x 128 cols u8) — independent of kb/vb
        for (int w = tid; w < 2048; w += 256) {
            int e = w >> 5, nl4 = (w & 31) << 2;
            *(unsigned int*)&qs[e][nl4] =
                *(const unsigned int*)(qS + (size_t)e * NDIM + nb + nl4);
        }
        __syncthreads();

        // M[e][d] * SCALE via popcount; 16 entries per thread
        {
            int e  = tid >> 2;
            int dd0 = (tid & 3) * 16;
            unsigned int kr[16];
            #pragma unroll
            for (int w = 0; w < 16; ++w) kr[w] = kb[e][w];
            #pragma unroll
            for (int dd = 0; dd < 16; ++dd) {
                int d = dd0 + dd;
                int s = 0;
                #pragma unroll
                for (int w = 0; w < 16; ++w) s += __popc(kr[w] & vb[d][w]);
                Ms[e][d] = (float)s * 0.125f;
            }
        }
        __syncthreads();

        // out[d][n] = sum_e q[e][n]*Ms[e][d]; LIF; fp16 spike write
        float acc[32];
        #pragma unroll
        for (int j = 0; j < 32; ++j) acc[j] = 0.f;

        #pragma unroll 4
        for (int e = 0; e < 64; ++e) {
            float qv = (float)qs[e][nLocal];
            #pragma unroll
            for (int j = 0; j < 32; ++j)
                acc[j] += qv * Ms[e][d0 + j];
        }

        const int n = nb + nLocal;
        __half2* stp = (__half2*)(st + ((size_t)b * NDIM + n) * CDIM + h * GDIM + d0);
        #pragma unroll
        for (int j2 = 0; j2 < 16; ++j2) {
            float m0 = memS[(d0 + 2*j2 + 0) * 128 + nLocal] * 0.5f + acc[2*j2 + 0];
            float m1 = memS[(d0 + 2*j2 + 1) * 128 + nLocal] * 0.5f + acc[2*j2 + 1];
            float s0 = (m0 > 1.0f) ? 1.0f : 0.0f; if (s0 != 0.0f) m0 = 0.f;
            float s1 = (m1 > 1.0f) ? 1.0f : 0.0f; if (s1 != 0.0f) m1 = 0.f;
            memS[(d0 + 2*j2 + 0) * 128 + nLocal] = m0;
            memS[(d0 + 2*j2 + 1) * 128 + nLocal] = m1;
            stp[j2] = __floats2half2_rn(s0, s1);
        }
    }
}

// ---------------------------------------------------------------------------
// Proj GEMM + BN (shared-operand HMMA, NP=2), 128x256 tile.
// ---------------------------------------------------------------------------
__device__ __forceinline__ void proj_load_chunk(
    const __half* __restrict__ A0, const __half* __restrict__ A1,
    const __half* __restrict__ B0,
    int mBase, int n0g, int kOff, uint32_t buf, int tid)
{
    #pragma unroll
    for (int it = 0; it < 16; ++it) {
        int i = tid + it * 256;
        int s = i & 7;
        const __half* g;
        uint32_t dst;
        if (i < 1024)      { int r = i >> 3;          g = A0 + (size_t)(mBase + r) * CDIM + kOff + s * 8; dst = 0u     + swz((uint32_t)(r*128 + s*16)); }
        else if (i < 2048) { int r = (i - 1024) >> 3; g = A1 + (size_t)(mBase + r) * CDIM + kOff + s * 8; dst = 16384u + swz((uint32_t)(r*128 + s*16)); }
        else               { int r = (i - 2048) >> 3; g = B0 + (size_t)(n0g  + r) * CDIM + kOff + s * 8; dst = 32768u + swz((uint32_t)(r*128 + s*16)); }
        cp_async16(buf + dst, g);
    }
}

__global__ void __launch_bounds__(256, 1)
proj_gemm(const __half* __restrict__ A0g, const __half* __restrict__ A1g,
          const __half* __restrict__ B0g,
          float* __restrict__ Ybase,
          const float* __restrict__ bg, const float* __restrict__ bb,
          const float* __restrict__ bm, const float* __restrict__ bv)
{
    extern __shared__ __align__(128) unsigned char dsm[];
    const uint32_t sbase = smem_u32(dsm);
    const int tid = threadIdx.x, lane = tid & 31, wid = tid >> 5;
    const int warpM = wid >> 2, warpN = wid & 3;
    const int b = blockIdx.z;
    const int mBase = blockIdx.y * 128;
    const int n0g   = blockIdx.x * 256;

    const __half* B0 = B0g + (size_t)b * CN;

    float acc[4][8][4];
    #pragma unroll
    for (int i = 0; i < 4; ++i)
        #pragma unroll
        for (int j = 0; j < 8; ++j)
            #pragma unroll
            for (int k = 0; k < 4; ++k) acc[i][j][k] = 0.f;

    proj_load_chunk(A0g, A1g, B0, mBase, n0g, 0, sbase, tid);
    asm volatile("cp.async.commit_group;");

    int buf = 0;
    #pragma unroll 1
    for (int c = 0; c < 8; ++c) {
        if (c < 7) {
            proj_load_chunk(A0g, A1g, B0, mBase, n0g, (c + 1) * 64,
                            sbase + (buf ^ 1) * PBUF, tid);
            asm volatile("cp.async.commit_group;");
            asm volatile("cp.async.wait_group 1;");
        } else {
            asm volatile("cp.async.wait_group 0;");
        }
        __syncthreads();

        const uint32_t base = sbase + buf * PBUF;
        #pragma unroll
        for (int ks = 0; ks < 4; ++ks) {
            uint32_t a0[4][4], a1[4][4];
            const int khA = ks * 16 + (lane >> 4) * 8;
            #pragma unroll
            for (int mt = 0; mt < 4; ++mt) {
                int row = warpM * 64 + mt * 16 + (lane & 7) + ((lane >> 3) & 1) * 8;
                uint32_t bo = swz((uint32_t)(row * 128 + khA * 2));
                LDSM4(a0[mt][0], a0[mt][1], a0[mt][2], a0[mt][3], base + bo);
                LDSM4(a1[mt][0], a1[mt][1], a1[mt][2], a1[mt][3], base + 16384u + bo);
            }
            const int khB = ks * 16 + ((lane >> 3) & 1) * 8;
            #pragma unroll
            for (int nt2 = 0; nt2 < 4; ++nt2) {
                int nrow = warpN * 64 + nt2 * 16 + (lane & 7) + ((lane >> 4) & 1) * 8;
                uint32_t bo = swz((uint32_t)(nrow * 128 + khB * 2));
                uint32_t rb[4];
                LDSM4(rb[0], rb[1], rb[2], rb[3], base + 32768u + bo);
                #pragma unroll
                for (int mt = 0; mt < 4; ++mt) {
                    mma16816(acc[mt][nt2*2+0], a0[mt], rb[0], rb[1]);
                    mma16816(acc[mt][nt2*2+1], a0[mt], rb[2], rb[3]);
                    mma16816(acc[mt][nt2*2+0], a1[mt], rb[0], rb[1]);
                    mma16816(acc[mt][nt2*2+1], a1[mt], rb[2], rb[3]);
                }
            }
        }
        __syncthreads();
        buf ^= 1;
    }

    #pragma unroll
    for (int mt = 0; mt < 4; ++mt) {
        int o0 = mBase + warpM * 64 + mt * 16 + (lane >> 2);
        #pragma unroll
        for (int hf = 0; hf < 2; ++hf) {
            int o = o0 + hf * 8;
            int bnIdx = 3 * CDIM + o;
            float* rowP = Ybase + ((size_t)b * CDIM + o) * NDIM;
            float inv  = bg[bnIdx] / sqrtf(bv[bnIdx] + EPSF);
            float bias = bb[bnIdx] - bm[bnIdx] * inv;
            #pragma unroll
            for (int nt = 0; nt < 8; ++nt) {
                int nn = n0g + warpN * 64 + nt * 8 + (lane & 3) * 2;
                float2 v;
                v.x = acc[mt][nt][hf * 2 + 0] * inv + bias;
                v.y = acc[mt][nt][hf * 2 + 1] * inv + bias;
                *(float2*)(rowP + nn) = v;
            }
        }
    }
}

// ---------------------------------------------------------------------------
// launch
// ---------------------------------------------------------------------------
extern "C" void kernel_launch(void* const* d_in, const int* in_sizes, int n_in,
                              void* d_out, int out_size)
{
    (void)in_sizes; (void)n_in; (void)out_size;
    const float* x  = (const float*)d_in[0];
    const float* wq = (const float*)d_in[1];
    const float* wk = (const float*)d_in[2];
    const float* wv = (const float*)d_in[3];
    const float* wp = (const float*)d_in[4];
    const float* bg = (const float*)d_in[5];
    const float* bb = (const float*)d_in[6];
    const float* bm = (const float*)d_in[7];
    const float* bv = (const float*)d_in[8];
    float* out = (float*)d_out;

    cudaFuncSetAttribute(qkv_gemm_lif, cudaFuncAttributeMaxDynamicSharedMemorySize, QSMEM);
    cudaFuncSetAttribute(proj_gemm,    cudaFuncAttributeMaxDynamicSharedMemorySize, PSMEM);
    cudaFuncSetAttribute(attn_lif,     cudaFuncAttributeMaxDynamicSharedMemorySize, ASMEM);

    unsigned char* spk;
    __half *w2, *wp2, *xt2, *st;
    cudaGetSymbolAddress((void**)&spk,  g_spk);
    cudaGetSymbolAddress((void**)&w2,   g_w2);
    cudaGetSymbolAddress((void**)&wp2,  g_wp2);
    cudaGetSymbolAddress((void**)&xt2,  g_xt2);
    cudaGetSymbolAddress((void**)&st,   g_st);

    // 1. splits
    wsplit_kernel<<<(MTOT_QKV*CDIM + 255)/256, 256>>>(wq, wk, wv, wp);
    xsplit_kernel<<<dim3(16,16,BDIM), dim3(32,8)>>>(x);

    // 2. fused qkv GEMM + BN + LIF -> spikes (u8)
    qkv_gemm_lif<<<dim3(NDIM/128, MTOT_QKV/128, BP), 256, QSMEM>>>(
        w2, w2 + (size_t)MTOT_QKV*CDIM, xt2, xt2 + (size_t)BDIM*CN,
        spk, bg, bb, bm, bv);

    // 3. fused attention + LIF -> final spikes (fp16, proj-ready layout)
    attn_lif<<<dim3(4, HH, BP), 256, ASMEM>>>(spk, st);

    // 4. proj GEMM + BN -> out
    proj_gemm<<<dim3(NDIM/256, CDIM/128, BDIM), 256, PSMEM>>>(
        wp2, wp2 + (size_t)CDIM*CDIM, st, out, bg, bb, bm, bv);
}

// round 9
// speedup vs baseline: 1.8692x; 1.8692x over previous
#include <cuda_runtime.h>
#include <cuda_fp16.h>
#include <cstdint>
#include <cmath>

#define CDIM 512
#define NDIM 512
#define BDIM 64
#define TT 4
#define BP 16           // BDIM / TT
#define HH 8
#define GDIM 64
#define EPSF 1e-5f
#define CN (CDIM*NDIM)  // 262144
#define MTOT_QKV 1536

// qkv fused kernel smem: stage = A0(16K)+A1(16K)+B0(16K)+B1(16K) = 64KB
#define QBUF 65536
#define QSMEM (2*QBUF + 65536)    // + 64KB membrane state = 196608

// proj kernel smem (256-wide B)
#define PBUF 98304
#define PSMEM (2*PBUF)

// ---------------------------------------------------------------------------
// Scratch (device globals: allocation-free per harness rules)
// ---------------------------------------------------------------------------
__device__ __half        g_w2  [2ull*MTOT_QKV*CDIM];          // qkv weight splits
__device__ __half        g_wp2 [2ull*CDIM*CDIM];              // proj weight splits
__device__ __half        g_xt2 [2ull*BDIM*CN];                // x splits, [s][b][n][c]
__device__ unsigned char g_spk [3ull*BDIM*CN];                // qkv spikes [w][b][c][n]
__device__ float         g_attn[(unsigned long long)BDIM*CN]; // attn out pre-LIF
__device__ unsigned char g_spk4[(unsigned long long)BDIM*CN]; // final spikes u8
__device__ __half        g_st  [(unsigned long long)BDIM*CN]; // final spikes fp16 [b][n][c]

// ---------------------------------------------------------------------------
// PTX helpers (baseline sm_80+, valid on compute_103 target)
// ---------------------------------------------------------------------------
__device__ __forceinline__ uint32_t smem_u32(const void* p) {
    uint32_t a;
    asm("{ .reg .u64 t; cvta.to.shared.u64 t, %1; cvt.u32.u64 %0, t; }" : "=r"(a) : "l"(p));
    return a;
}
#define LDSM4(r0,r1,r2,r3,addr) \
    asm volatile("ldmatrix.sync.aligned.m8n8.x4.shared.b16 {%0,%1,%2,%3}, [%4];" \
        : "=r"(r0),"=r"(r1),"=r"(r2),"=r"(r3) : "r"(addr))

__device__ __forceinline__ void mma16816(float* c, const uint32_t* a,
                                         uint32_t b0, uint32_t b1) {
    asm volatile("mma.sync.aligned.m16n8k16.row.col.f32.f16.f16.f32 "
        "{%0,%1,%2,%3}, {%4,%5,%6,%7}, {%8,%9}, {%0,%1,%2,%3};"
        : "+f"(c[0]), "+f"(c[1]), "+f"(c[2]), "+f"(c[3])
        : "r"(a[0]), "r"(a[1]), "r"(a[2]), "r"(a[3]), "r"(b0), "r"(b1));
}
__device__ __forceinline__ void cp_async16(uint32_t dst, const void* src) {
    asm volatile("cp.async.cg.shared.global [%0], [%1], 16;" :: "r"(dst), "l"(src));
}
__device__ __forceinline__ uint32_t swz(uint32_t bo) {
    return bo ^ (((bo >> 7) & 7u) << 4);
}

// ---------------------------------------------------------------------------
// Weight splits: w -> (fp16 hi, fp16 residual)
// ---------------------------------------------------------------------------
__global__ void wsplit_kernel(const float* __restrict__ wq, const float* __restrict__ wk,
                              const float* __restrict__ wv, const float* __restrict__ wp)
{
    int i = blockIdx.x * 256 + threadIdx.x;
    if (i < MTOT_QKV * CDIM) {
        int o = i >> 9;
        const float* src = (o < 512) ? wq : (o < 1024 ? wk : wv);
        float v = src[((o & 511) << 9) | (i & 511)];
        __half h0 = __float2half_rn(v);
        float r1 = v - __half2float(h0);
        g_w2[i] = h0;
        g_w2[(size_t)MTOT_QKV * CDIM + i] = __float2half_rn(r1);
    }
    if (i < CDIM * CDIM) {
        float v = wp[i];
        __half h0 = __float2half_rn(v);
        float r1 = v - __half2float(h0);
        g_wp2[i] = h0;
        g_wp2[(size_t)CDIM * CDIM + i] = __float2half_rn(r1);
    }
}

// ---------------------------------------------------------------------------
// x split + transpose: x[b][c][n] fp32 -> g_xt2[s][b][n][c] fp16 (2 splits)
// ---------------------------------------------------------------------------
__global__ void xsplit_kernel(const float* __restrict__ x)
{
    __shared__ float tile[32][33];
    const int b = blockIdx.z, c0 = blockIdx.y * 32, n0 = blockIdx.x * 32;
    const float* xb = x + (size_t)b * CN;
    const int tx = threadIdx.x, ty = threadIdx.y;   // 32 x 8
    #pragma unroll
    for (int r = 0; r < 4; ++r) {
        int cl = ty * 4 + r;
        tile[cl][tx] = xb[(size_t)(c0 + cl) * NDIM + n0 + tx];
    }
    __syncthreads();
    const size_t SEG = (size_t)BDIM * CN;
    #pragma unroll
    for (int r = 0; r < 4; ++r) {
        int nl = ty * 4 + r, cl = tx;
        float v = tile[cl][nl];
        __half h0 = __float2half_rn(v);
        float r1 = v - __half2float(h0);
        size_t o = ((size_t)b * NDIM + (n0 + nl)) * CDIM + c0 + cl;
        g_xt2[o] = h0;
        g_xt2[SEG + o] = __float2half_rn(r1);
    }
}

// spk4 u8 [b][c][n] -> fp16 transposed [b][n][c] (spikes exact in fp16)
__global__ void spkt_kernel()
{
    __shared__ unsigned char tile[32][33];
    const int b = blockIdx.z, c0 = blockIdx.y * 32, n0 = blockIdx.x * 32;
    const unsigned char* sb = g_spk4 + (size_t)b * CN;
    const int tx = threadIdx.x, ty = threadIdx.y;
    #pragma unroll
    for (int r = 0; r < 4; ++r) {
        int cl = ty * 4 + r;
        tile[cl][tx] = sb[(size_t)(c0 + cl) * NDIM + n0 + tx];
    }
    __syncthreads();
    #pragma unroll
    for (int r = 0; r < 4; ++r) {
        int nl = ty * 4 + r, cl = tx;
        g_st[((size_t)b * NDIM + (n0 + nl)) * CDIM + c0 + cl] =
            __float2half_rn((float)tile[cl][nl]);
    }
}

// ---------------------------------------------------------------------------
// Fused QKV: split-HMMA GEMM + BN + LIF scan over T, spikes out (u8).
// CTA: 128(M) x 128(N), grid.z = b' (16); inner loop t=0..3, b = t*16+b'.
// ---------------------------------------------------------------------------
__device__ __forceinline__ void qkv_load_chunk(
    const __half* __restrict__ A0, const __half* __restrict__ A1,
    const __half* __restrict__ B0, const __half* __restrict__ B1,
    int mBase, int n0g, int kOff, uint32_t buf, int tid)
{
    #pragma unroll
    for (int it = 0; it < 16; ++it) {
        int i = tid + it * 256;          // 0..4095
        int s = i & 7;
        int r = (i >> 3) & 127;
        int seg = i >> 10;               // 0:A0 1:A1 2:B0 3:B1
        const __half* g;
        if (seg == 0)      g = A0 + (size_t)(mBase + r) * CDIM + kOff + s * 8;
        else if (seg == 1) g = A1 + (size_t)(mBase + r) * CDIM + kOff + s * 8;
        else if (seg == 2) g = B0 + (size_t)(n0g  + r) * CDIM + kOff + s * 8;
        else               g = B1 + (size_t)(n0g  + r) * CDIM + kOff + s * 8;
        cp_async16(buf + (uint32_t)(seg << 14) + swz((uint32_t)(r * 128 + s * 16)), g);
    }
}

__global__ void __launch_bounds__(256, 1)
qkv_gemm_lif(const __half* __restrict__ A0g, const __half* __restrict__ A1g,
             const __half* __restrict__ B0base, const __half* __restrict__ B1base,
             unsigned char* __restrict__ spk,
             const float* __restrict__ bg, const float* __restrict__ bb,
             const float* __restrict__ bm, const float* __restrict__ bv)
{
    extern __shared__ __align__(128) unsigned char dsm[];
    const uint32_t sbase = smem_u32(dsm);
    float* memS = (float*)(dsm + 2 * QBUF);

    const int tid = threadIdx.x, lane = tid & 31, wid = tid >> 5;
    const int warpM = wid >> 2, warpN = wid & 3;       // 2 x 4 warps, 64x32 each
    const int bz    = blockIdx.z;                      // b' 0..15
    const int mBase = blockIdx.y * 128;
    const int n0g   = blockIdx.x * 128;

    float invR[4][2], biasR[4][2];
    size_t rowB[4][2];
    #pragma unroll
    for (int mt = 0; mt < 4; ++mt)
        #pragma unroll
        for (int hf = 0; hf < 2; ++hf) {
            int o = mBase + warpM * 64 + mt * 16 + (lane >> 2) + hf * 8;
            int w = o >> 9, c = o & 511;
            float inv = bg[w * CDIM + c] / sqrtf(bv[w * CDIM + c] + EPSF);
            invR[mt][hf]  = inv;
            biasR[mt][hf] = bb[w * CDIM + c] - bm[w * CDIM + c] * inv;
            rowB[mt][hf]  = (size_t)w * BDIM * CN + (size_t)c * NDIM;
        }

    #pragma unroll
    for (int idx = 0; idx < 64; ++idx) memS[idx * 256 + tid] = 0.f;

    float acc[4][4][4];
    #pragma unroll
    for (int i = 0; i < 4; ++i)
        #pragma unroll
        for (int j = 0; j < 4; ++j)
            #pragma unroll
            for (int k = 0; k < 4; ++k) acc[i][j][k] = 0.f;

    #pragma unroll 1
    for (int t = 0; t < TT; ++t) {
        const int b = t * BP + bz;
        const __half* B0 = B0base + (size_t)b * CN;
        const __half* B1 = B1base + (size_t)b * CN;

        qkv_load_chunk(A0g, A1g, B0, B1, mBase, n0g, 0, sbase, tid);
        asm volatile("cp.async.commit_group;");

        int buf = 0;
        #pragma unroll 1
        for (int c = 0; c < 8; ++c) {
            if (c < 7) {
                qkv_load_chunk(A0g, A1g, B0, B1, mBase, n0g, (c + 1) * 64,
                               sbase + (buf ^ 1) * QBUF, tid);
                asm volatile("cp.async.commit_group;");
                asm volatile("cp.async.wait_group 1;");
            } else {
                asm volatile("cp.async.wait_group 0;");
            }
            __syncthreads();

            const uint32_t base = sbase + buf * QBUF;
            #pragma unroll
            for (int ks = 0; ks < 4; ++ks) {
                uint32_t a0[4][4], a1[4][4];
                const int khA = ks * 16 + (lane >> 4) * 8;
                #pragma unroll
                for (int mt = 0; mt < 4; ++mt) {
                    int row = warpM * 64 + mt * 16 + (lane & 7) + ((lane >> 3) & 1) * 8;
                    uint32_t bo = swz((uint32_t)(row * 128 + khA * 2));
                    LDSM4(a0[mt][0], a0[mt][1], a0[mt][2], a0[mt][3], base + bo);
                    LDSM4(a1[mt][0], a1[mt][1], a1[mt][2], a1[mt][3], base + 16384u + bo);
                }
                const int khB = ks * 16 + ((lane >> 3) & 1) * 8;
                #pragma unroll
                for (int nt2 = 0; nt2 < 2; ++nt2) {
                    int nrow = warpN * 32 + nt2 * 16 + (lane & 7) + ((lane >> 4) & 1) * 8;
                    uint32_t bo = swz((uint32_t)(nrow * 128 + khB * 2));
                    uint32_t rb[4];
                    LDSM4(rb[0], rb[1], rb[2], rb[3], base + 32768u + bo);
                    #pragma unroll
                    for (int mt = 0; mt < 4; ++mt) {
                        mma16816(acc[mt][nt2*2+0], a0[mt], rb[0], rb[1]);
                        mma16816(acc[mt][nt2*2+1], a0[mt], rb[2], rb[3]);
                        mma16816(acc[mt][nt2*2+0], a1[mt], rb[0], rb[1]);
                        mma16816(acc[mt][nt2*2+1], a1[mt], rb[2], rb[3]);
                    }
                    LDSM4(rb[0], rb[1], rb[2], rb[3], base + 49152u + bo);
                    #pragma unroll
                    for (int mt = 0; mt < 4; ++mt) {
                        mma16816(acc[mt][nt2*2+0], a0[mt], rb[0], rb[1]);
                        mma16816(acc[mt][nt2*2+1], a0[mt], rb[2], rb[3]);
                    }
                }
            }
            __syncthreads();
            buf ^= 1;
        }

        // epilogue: BN + LIF step + spike write (per-thread-exclusive memS)
        #pragma unroll
        for (int mt = 0; mt < 4; ++mt)
            #pragma unroll
            for (int hf = 0; hf < 2; ++hf) {
                const float inv = invR[mt][hf], bias = biasR[mt][hf];
                unsigned char* ucRow = spk + rowB[mt][hf] + (size_t)b * CN;
                #pragma unroll
                for (int nt = 0; nt < 4; ++nt) {
                    int idx = mt * 16 + nt * 4 + hf * 2;
                    int nn  = n0g + warpN * 32 + nt * 8 + (lane & 3) * 2;
                    float pre0 = acc[mt][nt][hf*2+0] * inv + bias;
                    float pre1 = acc[mt][nt][hf*2+1] * inv + bias;
                    float m0 = memS[(idx+0) * 256 + tid] * 0.5f + pre0;
                    float m1 = memS[(idx+1) * 256 + tid] * 0.5f + pre1;
                    uchar2 s;
                    s.x = m0 > 1.0f; if (s.x) m0 = 0.f;
                    s.y = m1 > 1.0f; if (s.y) m1 = 0.f;
                    memS[(idx+0) * 256 + tid] = m0;
                    memS[(idx+1) * 256 + tid] = m1;
                    *(uchar2*)(ucRow + nn) = s;
                    acc[mt][nt][hf*2+0] = 0.f;
                    acc[mt][nt][hf*2+1] = 0.f;
                }
            }
    }
}

// ---------------------------------------------------------------------------
// Spiking attention (round-6 proven version): one CTA per (b,h),
// popcount M then q*M, writes fp32 g_attn.
// ---------------------------------------------------------------------------
__global__ void __launch_bounds__(256)
attn_kernel(const unsigned char* __restrict__ spk,
            float* __restrict__ attn)
{
    const int bh = blockIdx.x;
    const int b  = bh / HH;
    const int h  = bh % HH;
    const size_t head_off = ((size_t)b * CDIM + (size_t)h * GDIM) * NDIM;
    const unsigned char* qS = spk + 0ull * BDIM * CN + head_off;
    const unsigned char* kS = spk + 1ull * BDIM * CN + head_off;
    const unsigned char* vS = spk + 2ull * BDIM * CN + head_off;

    __shared__ unsigned int kb[64][16];
    __shared__ unsigned int vb[64][16];
    __shared__ float        Ms[64][64];
    __shared__ unsigned char qs[64][128];

    const int tid  = threadIdx.x;
    const int lane = tid & 31;
    const int warp = tid >> 5;

    #pragma unroll
    for (int r = 0; r < 8; ++r) {
        int e = warp * 8 + r;
        #pragma unroll
        for (int w = 0; w < 16; ++w) {
            unsigned int bkk = __ballot_sync(0xffffffffu, kS[(size_t)e * NDIM + w * 32 + lane] != 0);
            unsigned int bvv = __ballot_sync(0xffffffffu, vS[(size_t)e * NDIM + w * 32 + lane] != 0);
            if (lane == 0) { kb[e][w] = bkk; vb[e][w] = bvv; }
        }
    }
    __syncthreads();

    {
        int e  = tid >> 2;
        int d0 = (tid & 3) * 16;
        unsigned int kr[16];
        #pragma unroll
        for (int w = 0; w < 16; ++w) kr[w] = kb[e][w];
        #pragma unroll
        for (int dd = 0; dd < 16; ++dd) {
            int d = d0 + dd;
            int s = 0;
            #pragma unroll
            for (int w = 0; w < 16; ++w) s += __popc(kr[w] & vb[d][w]);
            Ms[e][d] = (float)s * 0.125f;
        }
    }
    __syncthreads();

    const int nLocal = tid & 127;
    const int d0     = (tid >> 7) * 32;
    float* outp = attn + head_off;

    for (int ch = 0; ch < 4; ++ch) {
        const int nb = ch * 128;
        for (int w = tid; w < 2048; w += 256) {
            int e = w >> 5, nl4 = (w & 31) << 2;
            *(unsigned int*)&qs[e][nl4] =
                *(const unsigned int*)(qS + (size_t)e * NDIM + nb + nl4);
        }
        __syncthreads();

        float acc[32];
        #pragma unroll
        for (int j = 0; j < 32; ++j) acc[j] = 0.f;

        #pragma unroll 4
        for (int e = 0; e < 64; ++e) {
            float qv = (float)qs[e][nLocal];
            #pragma unroll
            for (int j = 0; j < 32; ++j)
                acc[j] += qv * Ms[e][d0 + j];
        }
        #pragma unroll
        for (int j = 0; j < 32; ++j)
            outp[(size_t)(d0 + j) * NDIM + nb + nLocal] = acc[j];
        __syncthreads();
    }
}

// ---------------------------------------------------------------------------
// LIF scan (DRAM-roofline-bound)
// ---------------------------------------------------------------------------
__global__ void lif_kernel(const float* __restrict__ pre,
                           unsigned char* __restrict__ spk)
{
    size_t idx   = (size_t)blockIdx.x * blockDim.x + threadIdx.x;
    size_t total = (size_t)BP * (CN / 4);
    if (idx >= total) return;
    int j4 = (int)(idx % (CN / 4));
    int bp = (int)(idx / (CN / 4));

    float4 mem = make_float4(0.f, 0.f, 0.f, 0.f);
    #pragma unroll
    for (int t = 0; t < TT; ++t) {
        size_t off = (size_t)(t * BP + bp) * CN + (size_t)j4 * 4;
        float4 xi = *(const float4*)(pre + off);
        mem.x = mem.x * 0.5f + xi.x;
        mem.y = mem.y * 0.5f + xi.y;
        mem.z = mem.z * 0.5f + xi.z;
        mem.w = mem.w * 0.5f + xi.w;
        uchar4 sp;
        sp.x = mem.x > 1.0f; if (sp.x) mem.x = 0.f;
        sp.y = mem.y > 1.0f; if (sp.y) mem.y = 0.f;
        sp.z = mem.z > 1.0f; if (sp.z) mem.z = 0.f;
        sp.w = mem.w > 1.0f; if (sp.w) mem.w = 0.f;
        *(uchar4*)(spk + off) = sp;
    }
}

// ---------------------------------------------------------------------------
// Proj GEMM + BN (shared-operand HMMA, NP=2), 128x256 tile.
// ---------------------------------------------------------------------------
__device__ __forceinline__ void proj_load_chunk(
    const __half* __restrict__ A0, const __half* __restrict__ A1,
    const __half* __restrict__ B0,
    int mBase, int n0g, int kOff, uint32_t buf, int tid)
{
    #pragma unroll
    for (int it = 0; it < 16; ++it) {
        int i = tid + it * 256;
        int s = i & 7;
        const __half* g;
        uint32_t dst;
        if (i < 1024)      { int r = i >> 3;          g = A0 + (size_t)(mBase + r) * CDIM + kOff + s * 8; dst = 0u     + swz((uint32_t)(r*128 + s*16)); }
        else if (i < 2048) { int r = (i - 1024) >> 3; g = A1 + (size_t)(mBase + r) * CDIM + kOff + s * 8; dst = 16384u + swz((uint32_t)(r*128 + s*16)); }
        else               { int r = (i - 2048) >> 3; g = B0 + (size_t)(n0g  + r) * CDIM + kOff + s * 8; dst = 32768u + swz((uint32_t)(r*128 + s*16)); }
        cp_async16(buf + dst, g);
    }
}

__global__ void __launch_bounds__(256, 1)
proj_gemm(const __half* __restrict__ A0g, const __half* __restrict__ A1g,
          const __half* __restrict__ B0g,
          float* __restrict__ Ybase,
          const float* __restrict__ bg, const float* __restrict__ bb,
          const float* __restrict__ bm, const float* __restrict__ bv)
{
    extern __shared__ __align__(128) unsigned char dsm[];
    const uint32_t sbase = smem_u32(dsm);
    const int tid = threadIdx.x, lane = tid & 31, wid = tid >> 5;
    const int warpM = wid >> 2, warpN = wid & 3;
    const int b = blockIdx.z;
    const int mBase = blockIdx.y * 128;
    const int n0g   = blockIdx.x * 256;

    const __half* B0 = B0g + (size_t)b * CN;

    float acc[4][8][4];
    #pragma unroll
    for (int i = 0; i < 4; ++i)
        #pragma unroll
        for (int j = 0; j < 8; ++j)
            #pragma unroll
            for (int k = 0; k < 4; ++k) acc[i][j][k] = 0.f;

    proj_load_chunk(A0g, A1g, B0, mBase, n0g, 0, sbase, tid);
    asm volatile("cp.async.commit_group;");

    int buf = 0;
    #pragma unroll 1
    for (int c = 0; c < 8; ++c) {
        if (c < 7) {
            proj_load_chunk(A0g, A1g, B0, mBase, n0g, (c + 1) * 64,
                            sbase + (buf ^ 1) * PBUF, tid);
            asm volatile("cp.async.commit_group;");
            asm volatile("cp.async.wait_group 1;");
        } else {
            asm volatile("cp.async.wait_group 0;");
        }
        __syncthreads();

        const uint32_t base = sbase + buf * PBUF;
        #pragma unroll
        for (int ks = 0; ks < 4; ++ks) {
            uint32_t a0[4][4], a1[4][4];
            const int khA = ks * 16 + (lane >> 4) * 8;
            #pragma unroll
            for (int mt = 0; mt < 4; ++mt) {
                int row = warpM * 64 + mt * 16 + (lane & 7) + ((lane >> 3) & 1) * 8;
                uint32_t bo = swz((uint32_t)(row * 128 + khA * 2));
                LDSM4(a0[mt][0], a0[mt][1], a0[mt][2], a0[mt][3], base + bo);
                LDSM4(a1[mt][0], a1[mt][1], a1[mt][2], a1[mt][3], base + 16384u + bo);
            }
            const int khB = ks * 16 + ((lane >> 3) & 1) * 8;
            #pragma unroll
            for (int nt2 = 0; nt2 < 4; ++nt2) {
                int nrow = warpN * 64 + nt2 * 16 + (lane & 7) + ((lane >> 4) & 1) * 8;
                uint32_t bo = swz((uint32_t)(nrow * 128 + khB * 2));
                uint32_t rb[4];
                LDSM4(rb[0], rb[1], rb[2], rb[3], base + 32768u + bo);
                #pragma unroll
                for (int mt = 0; mt < 4; ++mt) {
                    mma16816(acc[mt][nt2*2+0], a0[mt], rb[0], rb[1]);
                    mma16816(acc[mt][nt2*2+1], a0[mt], rb[2], rb[3]);
                    mma16816(acc[mt][nt2*2+0], a1[mt], rb[0], rb[1]);
                    mma16816(acc[mt][nt2*2+1], a1[mt], rb[2], rb[3]);
                }
            }
        }
        __syncthreads();
        buf ^= 1;
    }

    #pragma unroll
    for (int mt = 0; mt < 4; ++mt) {
        int o0 = mBase + warpM * 64 + mt * 16 + (lane >> 2);
        #pragma unroll
        for (int hf = 0; hf < 2; ++hf) {
            int o = o0 + hf * 8;
            int bnIdx = 3 * CDIM + o;
            float* rowP = Ybase + ((size_t)b * CDIM + o) * NDIM;
            float inv  = bg[bnIdx] / sqrtf(bv[bnIdx] + EPSF);
            float bias = bb[bnIdx] - bm[bnIdx] * inv;
            #pragma unroll
            for (int nt = 0; nt < 8; ++nt) {
                int nn = n0g + warpN * 64 + nt * 8 + (lane & 3) * 2;
                float2 v;
                v.x = acc[mt][nt][hf * 2 + 0] * inv + bias;
                v.y = acc[mt][nt][hf * 2 + 1] * inv + bias;
                *(float2*)(rowP + nn) = v;
            }
        }
    }
}

// ---------------------------------------------------------------------------
// launch
// ---------------------------------------------------------------------------
extern "C" void kernel_launch(void* const* d_in, const int* in_sizes, int n_in,
                              void* d_out, int out_size)
{
    (void)in_sizes; (void)n_in; (void)out_size;
    const float* x  = (const float*)d_in[0];
    const float* wq = (const float*)d_in[1];
    const float* wk = (const float*)d_in[2];
    const float* wv = (const float*)d_in[3];
    const float* wp = (const float*)d_in[4];
    const float* bg = (const float*)d_in[5];
    const float* bb = (const float*)d_in[6];
    const float* bm = (const float*)d_in[7];
    const float* bv = (const float*)d_in[8];
    float* out = (float*)d_out;

    cudaFuncSetAttribute(qkv_gemm_lif, cudaFuncAttributeMaxDynamicSharedMemorySize, QSMEM);
    cudaFuncSetAttribute(proj_gemm,    cudaFuncAttributeMaxDynamicSharedMemorySize, PSMEM);

    unsigned char *spk, *spk4;
    float* attn;
    __half *w2, *wp2, *xt2, *st;
    cudaGetSymbolAddress((void**)&spk,  g_spk);
    cudaGetSymbolAddress((void**)&spk4, g_spk4);
    cudaGetSymbolAddress((void**)&attn, g_attn);
    cudaGetSymbolAddress((void**)&w2,   g_w2);
    cudaGetSymbolAddress((void**)&wp2,  g_wp2);
    cudaGetSymbolAddress((void**)&xt2,  g_xt2);
    cudaGetSymbolAddress((void**)&st,   g_st);

    // 1. splits
    wsplit_kernel<<<(MTOT_QKV*CDIM + 255)/256, 256>>>(wq, wk, wv, wp);
    xsplit_kernel<<<dim3(16,16,BDIM), dim3(32,8)>>>(x);

    // 2. fused qkv GEMM + BN + LIF -> spikes (u8)
    qkv_gemm_lif<<<dim3(NDIM/128, MTOT_QKV/128, BP), 256, QSMEM>>>(
        w2, w2 + (size_t)MTOT_QKV*CDIM, xt2, xt2 + (size_t)BDIM*CN,
        spk, bg, bb, bm, bv);

    // 3. spiking attention (proven round-6 kernel) -> fp32 pre-acts
    attn_kernel<<<BDIM * HH, 256>>>(spk, attn);

    // 4. LIF over attention output -> u8 spikes
    {
        size_t total = (size_t)BP * (CN / 4);
        lif_kernel<<<(int)((total + 255)/256), 256>>>(attn, spk4);
    }

    // 5. spike transpose to fp16 [b][n][c]
    spkt_kernel<<<dim3(16,16,BDIM), dim3(32,8)>>>();

    // 6. proj GEMM + BN -> out
    proj_gemm<<<dim3(NDIM/256, CDIM/128, BDIM), 256, PSMEM>>>(
        wp2, wp2 + (size_t)CDIM*CDIM, st, out, bg, bb, bm, bv);
}

// round 10
// speedup vs baseline: 1.9405x; 1.0381x over previous
#include <cuda_runtime.h>
#include <cuda_fp16.h>
#include <cstdint>
#include <cmath>

#define CDIM 512
#define NDIM 512
#define BDIM 64
#define TT 4
#define BP 16           // BDIM / TT
#define HH 8
#define GDIM 64
#define EPSF 1e-5f
#define CN (CDIM*NDIM)  // 262144
#define MTOT_QKV 1536

// qkv fused kernel smem: stage = A0(16K)+A1(16K)+B0(16K)+B1(16K) = 64KB
#define QBUF 65536
#define QSMEM (2*QBUF + 65536)    // + 64KB membrane state = 196608

// proj kernel smem (256-wide B)
#define PBUF 98304
#define PSMEM (2*PBUF)

// ---------------------------------------------------------------------------
// Scratch (device globals: allocation-free per harness rules)
// ---------------------------------------------------------------------------
__device__ __half        g_w2  [2ull*MTOT_QKV*CDIM];          // qkv weight splits
__device__ __half        g_wp2 [2ull*CDIM*CDIM];              // proj weight splits
__device__ __half        g_xt2 [2ull*BDIM*CN];                // x splits, [s][b][n][c]
__device__ unsigned char g_spk [3ull*BDIM*CN];                // qkv spikes [w][b][c][n]
__device__ float         g_attn[(unsigned long long)BDIM*CN]; // attn out pre-LIF
__device__ __half        g_st  [(unsigned long long)BDIM*CN]; // final spikes fp16 [b][n][c]

// ---------------------------------------------------------------------------
// PTX helpers (baseline sm_80+, valid on compute_103 target)
// ---------------------------------------------------------------------------
__device__ __forceinline__ uint32_t smem_u32(const void* p) {
    uint32_t a;
    asm("{ .reg .u64 t; cvta.to.shared.u64 t, %1; cvt.u32.u64 %0, t; }" : "=r"(a) : "l"(p));
    return a;
}
#define LDSM4(r0,r1,r2,r3,addr) \
    asm volatile("ldmatrix.sync.aligned.m8n8.x4.shared.b16 {%0,%1,%2,%3}, [%4];" \
        : "=r"(r0),"=r"(r1),"=r"(r2),"=r"(r3) : "r"(addr))

__device__ __forceinline__ void mma16816(float* c, const uint32_t* a,
                                         uint32_t b0, uint32_t b1) {
    asm volatile("mma.sync.aligned.m16n8k16.row.col.f32.f16.f16.f32 "
        "{%0,%1,%2,%3}, {%4,%5,%6,%7}, {%8,%9}, {%0,%1,%2,%3};"
        : "+f"(c[0]), "+f"(c[1]), "+f"(c[2]), "+f"(c[3])
        : "r"(a[0]), "r"(a[1]), "r"(a[2]), "r"(a[3]), "r"(b0), "r"(b1));
}
__device__ __forceinline__ void cp_async16(uint32_t dst, const void* src) {
    asm volatile("cp.async.cg.shared.global [%0], [%1], 16;" :: "r"(dst), "l"(src));
}
__device__ __forceinline__ uint32_t swz(uint32_t bo) {
    return bo ^ (((bo >> 7) & 7u) << 4);
}

// ---------------------------------------------------------------------------
// Weight splits: w -> (fp16 hi, fp16 residual)
// ---------------------------------------------------------------------------
__global__ void wsplit_kernel(const float* __restrict__ wq, const float* __restrict__ wk,
                              const float* __restrict__ wv, const float* __restrict__ wp)
{
    int i = blockIdx.x * 256 + threadIdx.x;
    if (i < MTOT_QKV * CDIM) {
        int o = i >> 9;
        const float* src = (o < 512) ? wq : (o < 1024 ? wk : wv);
        float v = src[((o & 511) << 9) | (i & 511)];
        __half h0 = __float2half_rn(v);
        float r1 = v - __half2float(h0);
        g_w2[i] = h0;
        g_w2[(size_t)MTOT_QKV * CDIM + i] = __float2half_rn(r1);
    }
    if (i < CDIM * CDIM) {
        float v = wp[i];
        __half h0 = __float2half_rn(v);
        float r1 = v - __half2float(h0);
        g_wp2[i] = h0;
        g_wp2[(size_t)CDIM * CDIM + i] = __float2half_rn(r1);
    }
}

// ---------------------------------------------------------------------------
// x split + transpose: x[b][c][n] fp32 -> g_xt2[s][b][n][c] fp16 (2 splits)
// ---------------------------------------------------------------------------
__global__ void xsplit_kernel(const float* __restrict__ x)
{
    __shared__ float tile[32][33];
    const int b = blockIdx.z, c0 = blockIdx.y * 32, n0 = blockIdx.x * 32;
    const float* xb = x + (size_t)b * CN;
    const int tx = threadIdx.x, ty = threadIdx.y;   // 32 x 8
    #pragma unroll
    for (int r = 0; r < 4; ++r) {
        int cl = ty * 4 + r;
        tile[cl][tx] = xb[(size_t)(c0 + cl) * NDIM + n0 + tx];
    }
    __syncthreads();
    const size_t SEG = (size_t)BDIM * CN;
    #pragma unroll
    for (int r = 0; r < 4; ++r) {
        int nl = ty * 4 + r, cl = tx;
        float v = tile[cl][nl];
        __half h0 = __float2half_rn(v);
        float r1 = v - __half2float(h0);
        size_t o = ((size_t)b * NDIM + (n0 + nl)) * CDIM + c0 + cl;
        g_xt2[o] = h0;
        g_xt2[SEG + o] = __float2half_rn(r1);
    }
}

// ---------------------------------------------------------------------------
// Fused QKV: split-HMMA GEMM + BN + LIF scan over T, spikes out (u8).
// CTA: 128(M) x 128(N), grid.z = b' (16); inner loop t=0..3, b = t*16+b'.
// ---------------------------------------------------------------------------
__device__ __forceinline__ void qkv_load_chunk(
    const __half* __restrict__ A0, const __half* __restrict__ A1,
    const __half* __restrict__ B0, const __half* __restrict__ B1,
    int mBase, int n0g, int kOff, uint32_t buf, int tid)
{
    #pragma unroll
    for (int it = 0; it < 16; ++it) {
        int i = tid + it * 256;          // 0..4095
        int s = i & 7;
        int r = (i >> 3) & 127;
        int seg = i >> 10;               // 0:A0 1:A1 2:B0 3:B1
        const __half* g;
        if (seg == 0)      g = A0 + (size_t)(mBase + r) * CDIM + kOff + s * 8;
        else if (seg == 1) g = A1 + (size_t)(mBase + r) * CDIM + kOff + s * 8;
        else if (seg == 2) g = B0 + (size_t)(n0g  + r) * CDIM + kOff + s * 8;
        else               g = B1 + (size_t)(n0g  + r) * CDIM + kOff + s * 8;
        cp_async16(buf + (uint32_t)(seg << 14) + swz((uint32_t)(r * 128 + s * 16)), g);
    }
}

__global__ void __launch_bounds__(256, 1)
qkv_gemm_lif(const __half* __restrict__ A0g, const __half* __restrict__ A1g,
             const __half* __restrict__ B0base, const __half* __restrict__ B1base,
             unsigned char* __restrict__ spk,
             const float* __restrict__ bg, const float* __restrict__ bb,
             const float* __restrict__ bm, const float* __restrict__ bv)
{
    extern __shared__ __align__(128) unsigned char dsm[];
    const uint32_t sbase = smem_u32(dsm);
    float* memS = (float*)(dsm + 2 * QBUF);

    const int tid = threadIdx.x, lane = tid & 31, wid = tid >> 5;
    const int warpM = wid >> 2, warpN = wid & 3;       // 2 x 4 warps, 64x32 each
    const int bz    = blockIdx.z;                      // b' 0..15
    const int mBase = blockIdx.y * 128;
    const int n0g   = blockIdx.x * 128;

    float invR[4][2], biasR[4][2];
    size_t rowB[4][2];
    #pragma unroll
    for (int mt = 0; mt < 4; ++mt)
        #pragma unroll
        for (int hf = 0; hf < 2; ++hf) {
            int o = mBase + warpM * 64 + mt * 16 + (lane >> 2) + hf * 8;
            int w = o >> 9, c = o & 511;
            float inv = bg[w * CDIM + c] / sqrtf(bv[w * CDIM + c] + EPSF);
            invR[mt][hf]  = inv;
            biasR[mt][hf] = bb[w * CDIM + c] - bm[w * CDIM + c] * inv;
            rowB[mt][hf]  = (size_t)w * BDIM * CN + (size_t)c * NDIM;
        }

    #pragma unroll
    for (int idx = 0; idx < 64; ++idx) memS[idx * 256 + tid] = 0.f;

    float acc[4][4][4];
    #pragma unroll
    for (int i = 0; i < 4; ++i)
        #pragma unroll
        for (int j = 0; j < 4; ++j)
            #pragma unroll
            for (int k = 0; k < 4; ++k) acc[i][j][k] = 0.f;

    #pragma unroll 1
    for (int t = 0; t < TT; ++t) {
        const int b = t * BP + bz;
        const __half* B0 = B0base + (size_t)b * CN;
        const __half* B1 = B1base + (size_t)b * CN;

        qkv_load_chunk(A0g, A1g, B0, B1, mBase, n0g, 0, sbase, tid);
        asm volatile("cp.async.commit_group;");

        int buf = 0;
        #pragma unroll 1
        for (int c = 0; c < 8; ++c) {
            if (c < 7) {
                qkv_load_chunk(A0g, A1g, B0, B1, mBase, n0g, (c + 1) * 64,
                               sbase + (buf ^ 1) * QBUF, tid);
                asm volatile("cp.async.commit_group;");
                asm volatile("cp.async.wait_group 1;");
            } else {
                asm volatile("cp.async.wait_group 0;");
            }
            __syncthreads();

            const uint32_t base = sbase + buf * QBUF;
            #pragma unroll
            for (int ks = 0; ks < 4; ++ks) {
                uint32_t a0[4][4], a1[4][4];
                const int khA = ks * 16 + (lane >> 4) * 8;
                #pragma unroll
                for (int mt = 0; mt < 4; ++mt) {
                    int row = warpM * 64 + mt * 16 + (lane & 7) + ((lane >> 3) & 1) * 8;
                    uint32_t bo = swz((uint32_t)(row * 128 + khA * 2));
                    LDSM4(a0[mt][0], a0[mt][1], a0[mt][2], a0[mt][3], base + bo);
                    LDSM4(a1[mt][0], a1[mt][1], a1[mt][2], a1[mt][3], base + 16384u + bo);
                }
                const int khB = ks * 16 + ((lane >> 3) & 1) * 8;
                #pragma unroll
                for (int nt2 = 0; nt2 < 2; ++nt2) {
                    int nrow = warpN * 32 + nt2 * 16 + (lane & 7) + ((lane >> 4) & 1) * 8;
                    uint32_t bo = swz((uint32_t)(nrow * 128 + khB * 2));
                    uint32_t rb[4];
                    LDSM4(rb[0], rb[1], rb[2], rb[3], base + 32768u + bo);
                    #pragma unroll
                    for (int mt = 0; mt < 4; ++mt) {
                        mma16816(acc[mt][nt2*2+0], a0[mt], rb[0], rb[1]);
                        mma16816(acc[mt][nt2*2+1], a0[mt], rb[2], rb[3]);
                        mma16816(acc[mt][nt2*2+0], a1[mt], rb[0], rb[1]);
                        mma16816(acc[mt][nt2*2+1], a1[mt], rb[2], rb[3]);
                    }
                    LDSM4(rb[0], rb[1], rb[2], rb[3], base + 49152u + bo);
                    #pragma unroll
                    for (int mt = 0; mt < 4; ++mt) {
                        mma16816(acc[mt][nt2*2+0], a0[mt], rb[0], rb[1]);
                        mma16816(acc[mt][nt2*2+1], a0[mt], rb[2], rb[3]);
                    }
                }
            }
            __syncthreads();
            buf ^= 1;
        }

        // epilogue: BN + LIF step + spike write (per-thread-exclusive memS)
        #pragma unroll
        for (int mt = 0; mt < 4; ++mt)
            #pragma unroll
            for (int hf = 0; hf < 2; ++hf) {
                const float inv = invR[mt][hf], bias = biasR[mt][hf];
                unsigned char* ucRow = spk + rowB[mt][hf] + (size_t)b * CN;
                #pragma unroll
                for (int nt = 0; nt < 4; ++nt) {
                    int idx = mt * 16 + nt * 4 + hf * 2;
                    int nn  = n0g + warpN * 32 + nt * 8 + (lane & 3) * 2;
                    float pre0 = acc[mt][nt][hf*2+0] * inv + bias;
                    float pre1 = acc[mt][nt][hf*2+1] * inv + bias;
                    float m0 = memS[(idx+0) * 256 + tid] * 0.5f + pre0;
                    float m1 = memS[(idx+1) * 256 + tid] * 0.5f + pre1;
                    uchar2 s;
                    s.x = m0 > 1.0f; if (s.x) m0 = 0.f;
                    s.y = m1 > 1.0f; if (s.y) m1 = 0.f;
                    memS[(idx+0) * 256 + tid] = m0;
                    memS[(idx+1) * 256 + tid] = m1;
                    *(uchar2*)(ucRow + nn) = s;
                    acc[mt][nt][hf*2+0] = 0.f;
                    acc[mt][nt][hf*2+1] = 0.f;
                }
            }
    }
}

// ---------------------------------------------------------------------------
// Spiking attention, 2D register-blocked (8d x 4n per thread).
// Per e-step: 2 broadcast LDS.128 (Ms) + 1 LDS.32 (q bytes) for 32 FMAs.
// ---------------------------------------------------------------------------
__global__ void __launch_bounds__(256)
attn_kernel(const unsigned char* __restrict__ spk,
            float* __restrict__ attn)
{
    const int bh = blockIdx.x;
    const int b  = bh / HH;
    const int h  = bh % HH;
    const size_t head_off = ((size_t)b * CDIM + (size_t)h * GDIM) * NDIM;
    const unsigned char* qS = spk + 0ull * BDIM * CN + head_off;
    const unsigned char* kS = spk + 1ull * BDIM * CN + head_off;
    const unsigned char* vS = spk + 2ull * BDIM * CN + head_off;

    __shared__ unsigned int kb[64][16];
    __shared__ unsigned int vb[64][16];
    __shared__ float        Ms[64][64];
    __shared__ unsigned char qs[64][128];

    const int tid  = threadIdx.x;
    const int lane = tid & 31;
    const int warp = tid >> 5;

    #pragma unroll
    for (int r = 0; r < 8; ++r) {
        int e = warp * 8 + r;
        #pragma unroll
        for (int w = 0; w < 16; ++w) {
            unsigned int bkk = __ballot_sync(0xffffffffu, kS[(size_t)e * NDIM + w * 32 + lane] != 0);
            unsigned int bvv = __ballot_sync(0xffffffffu, vS[(size_t)e * NDIM + w * 32 + lane] != 0);
            if (lane == 0) { kb[e][w] = bkk; vb[e][w] = bvv; }
        }
    }
    __syncthreads();

    {
        int e  = tid >> 2;
        int d0 = (tid & 3) * 16;
        unsigned int kr[16];
        #pragma unroll
        for (int w = 0; w < 16; ++w) kr[w] = kb[e][w];
        #pragma unroll
        for (int dd = 0; dd < 16; ++dd) {
            int d = d0 + dd;
            int s = 0;
            #pragma unroll
            for (int w = 0; w < 16; ++w) s += __popc(kr[w] & vb[d][w]);
            Ms[e][d] = (float)s * 0.125f;
        }
    }
    __syncthreads();

    const int ng = lane;            // n-group: n = ng*4 (4 consecutive n)
    const int dg = warp;            // d-group: d = dg*8 .. dg*8+7
    float* outp = attn + head_off;

    for (int ch = 0; ch < 4; ++ch) {
        const int nb = ch * 128;
        for (int w = tid; w < 2048; w += 256) {
            int e = w >> 5, nl4 = (w & 31) << 2;
            *(unsigned int*)&qs[e][nl4] =
                *(const unsigned int*)(qS + (size_t)e * NDIM + nb + nl4);
        }
        __syncthreads();

        float acc[8][4];
        #pragma unroll
        for (int j = 0; j < 8; ++j)
            #pragma unroll
            for (int i = 0; i < 4; ++i) acc[j][i] = 0.f;

        #pragma unroll 4
        for (int e = 0; e < 64; ++e) {
            unsigned int q4 = *(const unsigned int*)&qs[e][ng * 4];
            float4 ma = *(const float4*)&Ms[e][dg * 8];
            float4 mb = *(const float4*)&Ms[e][dg * 8 + 4];
            float qf0 = (float)( q4        & 255u);
            float qf1 = (float)((q4 >>  8) & 255u);
            float qf2 = (float)((q4 >> 16) & 255u);
            float qf3 = (float)( q4 >> 24);
            float mm[8] = { ma.x, ma.y, ma.z, ma.w, mb.x, mb.y, mb.z, mb.w };
            #pragma unroll
            for (int j = 0; j < 8; ++j) {
                acc[j][0] += mm[j] * qf0;
                acc[j][1] += mm[j] * qf1;
                acc[j][2] += mm[j] * qf2;
                acc[j][3] += mm[j] * qf3;
            }
        }
        #pragma unroll
        for (int j = 0; j < 8; ++j) {
            float4 v = make_float4(acc[j][0], acc[j][1], acc[j][2], acc[j][3]);
            *(float4*)(outp + (size_t)(dg * 8 + j) * NDIM + nb + ng * 4) = v;
        }
        __syncthreads();
    }
}

// ---------------------------------------------------------------------------
// Fused LIF + transpose: attn fp32 [b][c][n] -> spikes fp16 [b][n][c].
// Block handles a 32c x 32n tile; t-scan with per-thread membrane regs.
// ---------------------------------------------------------------------------
__global__ void lift_kernel(const float* __restrict__ attn, __half* __restrict__ st)
{
    __shared__ float tile[32][33];
    const int n0 = blockIdx.x * 32, c0 = blockIdx.y * 32, bp = blockIdx.z;
    const int tx = threadIdx.x, ty = threadIdx.y;   // 32 x 8

    float mem[4] = {0.f, 0.f, 0.f, 0.f};

    #pragma unroll
    for (int t = 0; t < TT; ++t) {
        const int b = t * BP + bp;
        const float* ab = attn + (size_t)b * CN;
        __syncthreads();   // tile reusable (prev readers done)
        #pragma unroll
        for (int r = 0; r < 4; ++r) {
            int cl = ty * 4 + r;
            tile[cl][tx] = ab[(size_t)(c0 + cl) * NDIM + n0 + tx];
        }
        __syncthreads();
        // owner: element (c = c0+tx, n = n0+ty*4+r)
        __half* sb = st + ((size_t)b * NDIM + n0) * CDIM + c0;
        #pragma unroll
        for (int r = 0; r < 4; ++r) {
            int nl = ty * 4 + r;
            float m = mem[r] * 0.5f + tile[tx][nl];
            float sv = (m > 1.0f) ? 1.0f : 0.0f;
            if (sv != 0.0f) m = 0.f;
            mem[r] = m;
            sb[(size_t)nl * CDIM + tx] = __float2half_rn(sv);
        }
    }
}

// ---------------------------------------------------------------------------
// Proj GEMM + BN (shared-operand HMMA, NP=2), 128x256 tile.
// ---------------------------------------------------------------------------
__device__ __forceinline__ void proj_load_chunk(
    const __half* __restrict__ A0, const __half* __restrict__ A1,
    const __half* __restrict__ B0,
    int mBase, int n0g, int kOff, uint32_t buf, int tid)
{
    #pragma unroll
    for (int it = 0; it < 16; ++it) {
        int i = tid + it * 256;
        int s = i & 7;
        const __half* g;
        uint32_t dst;
        if (i < 1024)      { int r = i >> 3;          g = A0 + (size_t)(mBase + r) * CDIM + kOff + s * 8; dst = 0u     + swz((uint32_t)(r*128 + s*16)); }
        else if (i < 2048) { int r = (i - 1024) >> 3; g = A1 + (size_t)(mBase + r) * CDIM + kOff + s * 8; dst = 16384u + swz((uint32_t)(r*128 + s*16)); }
        else               { int r = (i - 2048) >> 3; g = B0 + (size_t)(n0g  + r) * CDIM + kOff + s * 8; dst = 32768u + swz((uint32_t)(r*128 + s*16)); }
        cp_async16(buf + dst, g);
    }
}

__global__ void __launch_bounds__(256, 1)
proj_gemm(const __half* __restrict__ A0g, const __half* __restrict__ A1g,
          const __half* __restrict__ B0g,
          float* __restrict__ Ybase,
          const float* __restrict__ bg, const float* __restrict__ bb,
          const float* __restrict__ bm, const float* __restrict__ bv)
{
    extern __shared__ __align__(128) unsigned char dsm[];
    const uint32_t sbase = smem_u32(dsm);
    const int tid = threadIdx.x, lane = tid & 31, wid = tid >> 5;
    const int warpM = wid >> 2, warpN = wid & 3;
    const int b = blockIdx.z;
    const int mBase = blockIdx.y * 128;
    const int n0g   = blockIdx.x * 256;

    const __half* B0 = B0g + (size_t)b * CN;

    float acc[4][8][4];
    #pragma unroll
    for (int i = 0; i < 4; ++i)
        #pragma unroll
        for (int j = 0; j < 8; ++j)
            #pragma unroll
            for (int k = 0; k < 4; ++k) acc[i][j][k] = 0.f;

    proj_load_chunk(A0g, A1g, B0, mBase, n0g, 0, sbase, tid);
    asm volatile("cp.async.commit_group;");

    int buf = 0;
    #pragma unroll 1
    for (int c = 0; c < 8; ++c) {
        if (c < 7) {
            proj_load_chunk(A0g, A1g, B0, mBase, n0g, (c + 1) * 64,
                            sbase + (buf ^ 1) * PBUF, tid);
            asm volatile("cp.async.commit_group;");
            asm volatile("cp.async.wait_group 1;");
        } else {
            asm volatile("cp.async.wait_group 0;");
        }
        __syncthreads();

        const uint32_t base = sbase + buf * PBUF;
        #pragma unroll
        for (int ks = 0; ks < 4; ++ks) {
            uint32_t a0[4][4], a1[4][4];
            const int khA = ks * 16 + (lane >> 4) * 8;
            #pragma unroll
            for (int mt = 0; mt < 4; ++mt) {
                int row = warpM * 64 + mt * 16 + (lane & 7) + ((lane >> 3) & 1) * 8;
                uint32_t bo = swz((uint32_t)(row * 128 + khA * 2));
                LDSM4(a0[mt][0], a0[mt][1], a0[mt][2], a0[mt][3], base + bo);
                LDSM4(a1[mt][0], a1[mt][1], a1[mt][2], a1[mt][3], base + 16384u + bo);
            }
            const int khB = ks * 16 + ((lane >> 3) & 1) * 8;
            #pragma unroll
            for (int nt2 = 0; nt2 < 4; ++nt2) {
                int nrow = warpN * 64 + nt2 * 16 + (lane & 7) + ((lane >> 4) & 1) * 8;
                uint32_t bo = swz((uint32_t)(nrow * 128 + khB * 2));
                uint32_t rb[4];
                LDSM4(rb[0], rb[1], rb[2], rb[3], base + 32768u + bo);
                #pragma unroll
                for (int mt = 0; mt < 4; ++mt) {
                    mma16816(acc[mt][nt2*2+0], a0[mt], rb[0], rb[1]);
                    mma16816(acc[mt][nt2*2+1], a0[mt], rb[2], rb[3]);
                    mma16816(acc[mt][nt2*2+0], a1[mt], rb[0], rb[1]);
                    mma16816(acc[mt][nt2*2+1], a1[mt], rb[2], rb[3]);
                }
            }
        }
        __syncthreads();
        buf ^= 1;
    }

    #pragma unroll
    for (int mt = 0; mt < 4; ++mt) {
        int o0 = mBase + warpM * 64 + mt * 16 + (lane >> 2);
        #pragma unroll
        for (int hf = 0; hf < 2; ++hf) {
            int o = o0 + hf * 8;
            int bnIdx = 3 * CDIM + o;
            float* rowP = Ybase + ((size_t)b * CDIM + o) * NDIM;
            float inv  = bg[bnIdx] / sqrtf(bv[bnIdx] + EPSF);
            float bias = bb[bnIdx] - bm[bnIdx] * inv;
            #pragma unroll
            for (int nt = 0; nt < 8; ++nt) {
                int nn = n0g + warpN * 64 + nt * 8 + (lane & 3) * 2;
                float2 v;
                v.x = acc[mt][nt][hf * 2 + 0] * inv + bias;
                v.y = acc[mt][nt][hf * 2 + 1] * inv + bias;
                *(float2*)(rowP + nn) = v;
            }
        }
    }
}

// ---------------------------------------------------------------------------
// launch
// ---------------------------------------------------------------------------
extern "C" void kernel_launch(void* const* d_in, const int* in_sizes, int n_in,
                              void* d_out, int out_size)
{
    (void)in_sizes; (void)n_in; (void)out_size;
    const float* x  = (const float*)d_in[0];
    const float* wq = (const float*)d_in[1];
    const float* wk = (const float*)d_in[2];
    const float* wv = (const float*)d_in[3];
    const float* wp = (const float*)d_in[4];
    const float* bg = (const float*)d_in[5];
    const float* bb = (const float*)d_in[6];
    const float* bm = (const float*)d_in[7];
    const float* bv = (const float*)d_in[8];
    float* out = (float*)d_out;

    cudaFuncSetAttribute(qkv_gemm_lif, cudaFuncAttributeMaxDynamicSharedMemorySize, QSMEM);
    cudaFuncSetAttribute(proj_gemm,    cudaFuncAttributeMaxDynamicSharedMemorySize, PSMEM);

    unsigned char *spk;
    float* attn;
    __half *w2, *wp2, *xt2, *st;
    cudaGetSymbolAddress((void**)&spk,  g_spk);
    cudaGetSymbolAddress((void**)&attn, g_attn);
    cudaGetSymbolAddress((void**)&w2,   g_w2);
    cudaGetSymbolAddress((void**)&wp2,  g_wp2);
    cudaGetSymbolAddress((void**)&xt2,  g_xt2);
    cudaGetSymbolAddress((void**)&st,   g_st);

    // 1. splits
    wsplit_kernel<<<(MTOT_QKV*CDIM + 255)/256, 256>>>(wq, wk, wv, wp);
    xsplit_kernel<<<dim3(16,16,BDIM), dim3(32,8)>>>(x);

    // 2. fused qkv GEMM + BN + LIF -> spikes (u8)
    qkv_gemm_lif<<<dim3(NDIM/128, MTOT_QKV/128, BP), 256, QSMEM>>>(
        w2, w2 + (size_t)MTOT_QKV*CDIM, xt2, xt2 + (size_t)BDIM*CN,
        spk, bg, bb, bm, bv);

    // 3. spiking attention (2D register-blocked) -> fp32 pre-acts
    attn_kernel<<<BDIM * HH, 256>>>(spk, attn);

    // 4. fused LIF + transpose -> fp16 spikes [b][n][c]
    lift_kernel<<<dim3(16, 16, BP), dim3(32, 8)>>>(attn, st);

    // 5. proj GEMM + BN -> out
    proj_gemm<<<dim3(NDIM/256, CDIM/128, BDIM), 256, PSMEM>>>(
        wp2, wp2 + (size_t)CDIM*CDIM, st, out, bg, bb, bm, bv);
}

// round 11
// speedup vs baseline: 2.0667x; 1.0650x over previous
#include <cuda_runtime.h>
#include <cuda_fp16.h>
#include <cstdint>
#include <cmath>

#define CDIM 512
#define NDIM 512
#define BDIM 64
#define TT 4
#define BP 16           // BDIM / TT
#define HH 8
#define GDIM 64
#define EPSF 1e-5f
#define CN (CDIM*NDIM)  // 262144
#define MTOT_QKV 1536

// qkv fused kernel smem: stage = A0(16K)+A1(16K)+B0(16K)+B1(16K) = 64KB
#define QBUF 65536
#define QSMEM (2*QBUF + 65536)    // + 64KB membrane state = 196608

// proj kernel smem (256-wide B)
#define PBUF 98304
#define PSMEM (2*PBUF)

// attn smem: kb(4K) + vb(4K) + MsT fp16(8K) + qf fp16 [64][512](64K)
#define ASMEM 81920

// ---------------------------------------------------------------------------
// Scratch (device globals: allocation-free per harness rules)
// ---------------------------------------------------------------------------
__device__ __half        g_w2  [2ull*MTOT_QKV*CDIM];          // qkv weight splits
__device__ __half        g_wp2 [2ull*CDIM*CDIM];              // proj weight splits
__device__ __half        g_xt2 [2ull*BDIM*CN];                // x splits, [s][b][n][c]
__device__ unsigned char g_spk [3ull*BDIM*CN];                // qkv spikes [w][b][c][n]
__device__ float         g_attn[(unsigned long long)BDIM*CN]; // attn out pre-LIF
__device__ __half        g_st  [(unsigned long long)BDIM*CN]; // final spikes fp16 [b][n][c]

// ---------------------------------------------------------------------------
// PTX helpers (baseline sm_80+, valid on compute_103 target)
// ---------------------------------------------------------------------------
__device__ __forceinline__ uint32_t smem_u32(const void* p) {
    uint32_t a;
    asm("{ .reg .u64 t; cvta.to.shared.u64 t, %1; cvt.u32.u64 %0, t; }" : "=r"(a) : "l"(p));
    return a;
}
#define LDSM4(r0,r1,r2,r3,addr) \
    asm volatile("ldmatrix.sync.aligned.m8n8.x4.shared.b16 {%0,%1,%2,%3}, [%4];" \
        : "=r"(r0),"=r"(r1),"=r"(r2),"=r"(r3) : "r"(addr))
#define LDSM4T(r0,r1,r2,r3,addr) \
    asm volatile("ldmatrix.sync.aligned.m8n8.x4.trans.shared.b16 {%0,%1,%2,%3}, [%4];" \
        : "=r"(r0),"=r"(r1),"=r"(r2),"=r"(r3) : "r"(addr))

__device__ __forceinline__ void mma16816(float* c, const uint32_t* a,
                                         uint32_t b0, uint32_t b1) {
    asm volatile("mma.sync.aligned.m16n8k16.row.col.f32.f16.f16.f32 "
        "{%0,%1,%2,%3}, {%4,%5,%6,%7}, {%8,%9}, {%0,%1,%2,%3};"
        : "+f"(c[0]), "+f"(c[1]), "+f"(c[2]), "+f"(c[3])
        : "r"(a[0]), "r"(a[1]), "r"(a[2]), "r"(a[3]), "r"(b0), "r"(b1));
}
__device__ __forceinline__ void cp_async16(uint32_t dst, const void* src) {
    asm volatile("cp.async.cg.shared.global [%0], [%1], 16;" :: "r"(dst), "l"(src));
}
__device__ __forceinline__ uint32_t swz(uint32_t bo) {
    return bo ^ (((bo >> 7) & 7u) << 4);
}

// ---------------------------------------------------------------------------
// Weight splits: w -> (fp16 hi, fp16 residual)
// ---------------------------------------------------------------------------
__global__ void wsplit_kernel(const float* __restrict__ wq, const float* __restrict__ wk,
                              const float* __restrict__ wv, const float* __restrict__ wp)
{
    int i = blockIdx.x * 256 + threadIdx.x;
    if (i < MTOT_QKV * CDIM) {
        int o = i >> 9;
        const float* src = (o < 512) ? wq : (o < 1024 ? wk : wv);
        float v = src[((o & 511) << 9) | (i & 511)];
        __half h0 = __float2half_rn(v);
        float r1 = v - __half2float(h0);
        g_w2[i] = h0;
        g_w2[(size_t)MTOT_QKV * CDIM + i] = __float2half_rn(r1);
    }
    if (i < CDIM * CDIM) {
        float v = wp[i];
        __half h0 = __float2half_rn(v);
        float r1 = v - __half2float(h0);
        g_wp2[i] = h0;
        g_wp2[(size_t)CDIM * CDIM + i] = __float2half_rn(r1);
    }
}

// ---------------------------------------------------------------------------
// x split + transpose: x[b][c][n] fp32 -> g_xt2[s][b][n][c] fp16 (2 splits)
// ---------------------------------------------------------------------------
__global__ void xsplit_kernel(const float* __restrict__ x)
{
    __shared__ float tile[32][33];
    const int b = blockIdx.z, c0 = blockIdx.y * 32, n0 = blockIdx.x * 32;
    const float* xb = x + (size_t)b * CN;
    const int tx = threadIdx.x, ty = threadIdx.y;   // 32 x 8
    #pragma unroll
    for (int r = 0; r < 4; ++r) {
        int cl = ty * 4 + r;
        tile[cl][tx] = xb[(size_t)(c0 + cl) * NDIM + n0 + tx];
    }
    __syncthreads();
    const size_t SEG = (size_t)BDIM * CN;
    #pragma unroll
    for (int r = 0; r < 4; ++r) {
        int nl = ty * 4 + r, cl = tx;
        float v = tile[cl][nl];
        __half h0 = __float2half_rn(v);
        float r1 = v - __half2float(h0);
        size_t o = ((size_t)b * NDIM + (n0 + nl)) * CDIM + c0 + cl;
        g_xt2[o] = h0;
        g_xt2[SEG + o] = __float2half_rn(r1);
    }
}

// ---------------------------------------------------------------------------
// Fused QKV: split-HMMA GEMM + BN + LIF scan over T, spikes out (u8).
// CTA: 128(M) x 128(N), grid.z = b' (16); inner loop t=0..3, b = t*16+b'.
// ---------------------------------------------------------------------------
__device__ __forceinline__ void qkv_load_chunk(
    const __half* __restrict__ A0, const __half* __restrict__ A1,
    const __half* __restrict__ B0, const __half* __restrict__ B1,
    int mBase, int n0g, int kOff, uint32_t buf, int tid)
{
    #pragma unroll
    for (int it = 0; it < 16; ++it) {
        int i = tid + it * 256;          // 0..4095
        int s = i & 7;
        int r = (i >> 3) & 127;
        int seg = i >> 10;               // 0:A0 1:A1 2:B0 3:B1
        const __half* g;
        if (seg == 0)      g = A0 + (size_t)(mBase + r) * CDIM + kOff + s * 8;
        else if (seg == 1) g = A1 + (size_t)(mBase + r) * CDIM + kOff + s * 8;
        else if (seg == 2) g = B0 + (size_t)(n0g  + r) * CDIM + kOff + s * 8;
        else               g = B1 + (size_t)(n0g  + r) * CDIM + kOff + s * 8;
        cp_async16(buf + (uint32_t)(seg << 14) + swz((uint32_t)(r * 128 + s * 16)), g);
    }
}

__global__ void __launch_bounds__(256, 1)
qkv_gemm_lif(const __half* __restrict__ A0g, const __half* __restrict__ A1g,
             const __half* __restrict__ B0base, const __half* __restrict__ B1base,
             unsigned char* __restrict__ spk,
             const float* __restrict__ bg, const float* __restrict__ bb,
             const float* __restrict__ bm, const float* __restrict__ bv)
{
    extern __shared__ __align__(128) unsigned char dsm[];
    const uint32_t sbase = smem_u32(dsm);
    float* memS = (float*)(dsm + 2 * QBUF);

    const int tid = threadIdx.x, lane = tid & 31, wid = tid >> 5;
    const int warpM = wid >> 2, warpN = wid & 3;       // 2 x 4 warps, 64x32 each
    const int bz    = blockIdx.z;                      // b' 0..15
    const int mBase = blockIdx.y * 128;
    const int n0g   = blockIdx.x * 128;

    float invR[4][2], biasR[4][2];
    size_t rowB[4][2];
    #pragma unroll
    for (int mt = 0; mt < 4; ++mt)
        #pragma unroll
        for (int hf = 0; hf < 2; ++hf) {
            int o = mBase + warpM * 64 + mt * 16 + (lane >> 2) + hf * 8;
            int w = o >> 9, c = o & 511;
            float inv = bg[w * CDIM + c] / sqrtf(bv[w * CDIM + c] + EPSF);
            invR[mt][hf]  = inv;
            biasR[mt][hf] = bb[w * CDIM + c] - bm[w * CDIM + c] * inv;
            rowB[mt][hf]  = (size_t)w * BDIM * CN + (size_t)c * NDIM;
        }

    #pragma unroll
    for (int idx = 0; idx < 64; ++idx) memS[idx * 256 + tid] = 0.f;

    float acc[4][4][4];
    #pragma unroll
    for (int i = 0; i < 4; ++i)
        #pragma unroll
        for (int j = 0; j < 4; ++j)
            #pragma unroll
            for (int k = 0; k < 4; ++k) acc[i][j][k] = 0.f;

    #pragma unroll 1
    for (int t = 0; t < TT; ++t) {
        const int b = t * BP + bz;
        const __half* B0 = B0base + (size_t)b * CN;
        const __half* B1 = B1base + (size_t)b * CN;

        qkv_load_chunk(A0g, A1g, B0, B1, mBase, n0g, 0, sbase, tid);
        asm volatile("cp.async.commit_group;");

        int buf = 0;
        #pragma unroll 1
        for (int c = 0; c < 8; ++c) {
            if (c < 7) {
                qkv_load_chunk(A0g, A1g, B0, B1, mBase, n0g, (c + 1) * 64,
                               sbase + (buf ^ 1) * QBUF, tid);
                asm volatile("cp.async.commit_group;");
                asm volatile("cp.async.wait_group 1;");
            } else {
                asm volatile("cp.async.wait_group 0;");
            }
            __syncthreads();

            const uint32_t base = sbase + buf * QBUF;
            #pragma unroll
            for (int ks = 0; ks < 4; ++ks) {
                uint32_t a0[4][4], a1[4][4];
                const int khA = ks * 16 + (lane >> 4) * 8;
                #pragma unroll
                for (int mt = 0; mt < 4; ++mt) {
                    int row = warpM * 64 + mt * 16 + (lane & 7) + ((lane >> 3) & 1) * 8;
                    uint32_t bo = swz((uint32_t)(row * 128 + khA * 2));
                    LDSM4(a0[mt][0], a0[mt][1], a0[mt][2], a0[mt][3], base + bo);
                    LDSM4(a1[mt][0], a1[mt][1], a1[mt][2], a1[mt][3], base + 16384u + bo);
                }
                const int khB = ks * 16 + ((lane >> 3) & 1) * 8;
                #pragma unroll
                for (int nt2 = 0; nt2 < 2; ++nt2) {
                    int nrow = warpN * 32 + nt2 * 16 + (lane & 7) + ((lane >> 4) & 1) * 8;
                    uint32_t bo = swz((uint32_t)(nrow * 128 + khB * 2));
                    uint32_t rb[4];
                    LDSM4(rb[0], rb[1], rb[2], rb[3], base + 32768u + bo);
                    #pragma unroll
                    for (int mt = 0; mt < 4; ++mt) {
                        mma16816(acc[mt][nt2*2+0], a0[mt], rb[0], rb[1]);
                        mma16816(acc[mt][nt2*2+1], a0[mt], rb[2], rb[3]);
                        mma16816(acc[mt][nt2*2+0], a1[mt], rb[0], rb[1]);
                        mma16816(acc[mt][nt2*2+1], a1[mt], rb[2], rb[3]);
                    }
                    LDSM4(rb[0], rb[1], rb[2], rb[3], base + 49152u + bo);
                    #pragma unroll
                    for (int mt = 0; mt < 4; ++mt) {
                        mma16816(acc[mt][nt2*2+0], a0[mt], rb[0], rb[1]);
                        mma16816(acc[mt][nt2*2+1], a0[mt], rb[2], rb[3]);
                    }
                }
            }
            __syncthreads();
            buf ^= 1;
        }

        // epilogue: BN + LIF step + spike write (per-thread-exclusive memS)
        #pragma unroll
        for (int mt = 0; mt < 4; ++mt)
            #pragma unroll
            for (int hf = 0; hf < 2; ++hf) {
                const float inv = invR[mt][hf], bias = biasR[mt][hf];
                unsigned char* ucRow = spk + rowB[mt][hf] + (size_t)b * CN;
                #pragma unroll
                for (int nt = 0; nt < 4; ++nt) {
                    int idx = mt * 16 + nt * 4 + hf * 2;
                    int nn  = n0g + warpN * 32 + nt * 8 + (lane & 3) * 2;
                    float pre0 = acc[mt][nt][hf*2+0] * inv + bias;
                    float pre1 = acc[mt][nt][hf*2+1] * inv + bias;
                    float m0 = memS[(idx+0) * 256 + tid] * 0.5f + pre0;
                    float m1 = memS[(idx+1) * 256 + tid] * 0.5f + pre1;
                    uchar2 s;
                    s.x = m0 > 1.0f; if (s.x) m0 = 0.f;
                    s.y = m1 > 1.0f; if (s.y) m1 = 0.f;
                    memS[(idx+0) * 256 + tid] = m0;
                    memS[(idx+1) * 256 + tid] = m1;
                    *(uchar2*)(ucRow + nn) = s;
                    acc[mt][nt][hf*2+0] = 0.f;
                    acc[mt][nt][hf*2+1] = 0.f;
                }
            }
    }
}

// ---------------------------------------------------------------------------
// Spiking attention via HMMA (exact): out[d][n] = sum_e MsT[d][e] * q[e][n].
// Ms entries (popcount*0.125 <= 64) and q (0/1) are exact in fp16; fp32
// accumulation of <=64 such terms is exact -> bit-identical to FFMA version.
// One CTA per (b,h), 8 warps each owning a 64-wide n slab.
// ---------------------------------------------------------------------------
__global__ void __launch_bounds__(256)
attn_kernel(const unsigned char* __restrict__ spk,
            float* __restrict__ attn)
{
    extern __shared__ __align__(128) unsigned char asmem[];
    unsigned int (*kb)[16] = (unsigned int (*)[16])(asmem);
    unsigned int (*vb)[16] = (unsigned int (*)[16])(asmem + 4096);
    const uint32_t msBase = smem_u32(asmem) + 8192;   // MsT fp16 [64][64], 128B rows, swz
    const uint32_t qfBase = smem_u32(asmem) + 16384;  // qf  fp16 [64][512], 1024B rows, XOR sw
    char* msPtr = (char*)asmem + 8192;
    char* qfPtr = (char*)asmem + 16384;

    const int bh = blockIdx.x;
    const int b  = bh / HH;
    const int h  = bh % HH;
    const size_t head_off = ((size_t)b * CDIM + (size_t)h * GDIM) * NDIM;
    const unsigned char* qS = spk + 0ull * BDIM * CN + head_off;
    const unsigned char* kS = spk + 1ull * BDIM * CN + head_off;
    const unsigned char* vS = spk + 2ull * BDIM * CN + head_off;

    const int tid  = threadIdx.x;
    const int lane = tid & 31;
    const int warp = tid >> 5;

    // Phase A: bitpack k/v via ballot; convert q u8 -> fp16 slab (independent)
    #pragma unroll
    for (int r = 0; r < 8; ++r) {
        int e = warp * 8 + r;
        #pragma unroll
        for (int w = 0; w < 16; ++w) {
            unsigned int bkk = __ballot_sync(0xffffffffu, kS[(size_t)e * NDIM + w * 32 + lane] != 0);
            unsigned int bvv = __ballot_sync(0xffffffffu, vS[(size_t)e * NDIM + w * 32 + lane] != 0);
            if (lane == 0) { kb[e][w] = bkk; vb[e][w] = bvv; }
        }
    }
    for (int i = tid; i < 8192; i += 256) {       // 8192 u32 = 64 x 512 bytes
        int e  = i >> 7;
        int n4 = (i & 127) * 4;
        unsigned int q4 = *(const unsigned int*)(qS + (size_t)e * NDIM + n4);
        __half2 h01 = __floats2half2_rn((float)( q4        & 255u),
                                        (float)((q4 >>  8) & 255u));
        __half2 h23 = __floats2half2_rn((float)((q4 >> 16) & 255u),
                                        (float)( q4 >> 24));
        uint32_t bo = ((uint32_t)(n4 * 2)) ^ (((uint32_t)e & 7u) << 4);
        char* p = qfPtr + (size_t)e * 1024 + bo;
        *(__half2*)(p)     = h01;
        *(__half2*)(p + 4) = h23;
    }
    __syncthreads();

    // Phase B: popcount M, store transposed fp16 (exact): MsT[d][e]
    {
        int e  = tid >> 2;
        int d0 = (tid & 3) * 16;
        unsigned int kr[16];
        #pragma unroll
        for (int w = 0; w < 16; ++w) kr[w] = kb[e][w];
        #pragma unroll
        for (int dd = 0; dd < 16; ++dd) {
            int d = d0 + dd;
            int s = 0;
            #pragma unroll
            for (int w = 0; w < 16; ++w) s += __popc(kr[w] & vb[d][w]);
            *(__half*)(msPtr + swz((uint32_t)(d * 128 + e * 2))) =
                __float2half_rn((float)s * 0.125f);
        }
    }
    __syncthreads();

    // Phase C: HMMA.  M=64(d) x N=64(n per warp) x K=64(e).
    float acc[4][8][4];
    #pragma unroll
    for (int i = 0; i < 4; ++i)
        #pragma unroll
        for (int j = 0; j < 8; ++j)
            #pragma unroll
            for (int k = 0; k < 4; ++k) acc[i][j][k] = 0.f;

    const int nWarp = warp * 64;
    #pragma unroll
    for (int ks = 0; ks < 4; ++ks) {
        // A: MsT row-major [d][e], plain ldmatrix (GEMM-A pattern)
        uint32_t af[4][4];
        const int khA = ks * 16 + (lane >> 4) * 8;
        #pragma unroll
        for (int mt = 0; mt < 4; ++mt) {
            int row = mt * 16 + (lane & 7) + ((lane >> 3) & 1) * 8;
            LDSM4(af[mt][0], af[mt][1], af[mt][2], af[mt][3],
                  msBase + swz((uint32_t)(row * 128 + khA * 2)));
        }
        // B: q k-major [e][n], ldmatrix.trans (B^T recipe)
        #pragma unroll
        for (int nt = 0; nt < 4; ++nt) {
            int eRow = ks * 16 + ((lane >> 3) & 1) * 8 + (lane & 7);
            int nCol = nWarp + nt * 16 + ((lane >> 4) & 1) * 8;
            uint32_t bo = ((uint32_t)(nCol * 2)) ^ (((uint32_t)eRow & 7u) << 4);
            uint32_t rb[4];
            LDSM4T(rb[0], rb[1], rb[2], rb[3],
                   qfBase + (uint32_t)(eRow * 1024) + bo);
            #pragma unroll
            for (int mt = 0; mt < 4; ++mt) {
                mma16816(acc[mt][nt*2+0], af[mt], rb[0], rb[1]);
                mma16816(acc[mt][nt*2+1], af[mt], rb[2], rb[3]);
            }
        }
    }

    // epilogue: write out[d][n] (d = head-local channel row)
    float* outp = attn + head_off;
    #pragma unroll
    for (int mt = 0; mt < 4; ++mt) {
        int dr0 = mt * 16 + (lane >> 2);
        #pragma unroll
        for (int nt8 = 0; nt8 < 8; ++nt8) {
            int n0 = nWarp + nt8 * 8 + (lane & 3) * 2;
            *(float2*)(outp + (size_t)dr0       * NDIM + n0) =
                make_float2(acc[mt][nt8][0], acc[mt][nt8][1]);
            *(float2*)(outp + (size_t)(dr0 + 8) * NDIM + n0) =
                make_float2(acc[mt][nt8][2], acc[mt][nt8][3]);
        }
    }
}

// ---------------------------------------------------------------------------
// Fused LIF + transpose: attn fp32 [b][c][n] -> spikes fp16 [b][n][c].
// Block handles a 32c x 32n tile; t-scan with per-thread membrane regs.
// ---------------------------------------------------------------------------
__global__ void lift_kernel(const float* __restrict__ attn, __half* __restrict__ st)
{
    __shared__ float tile[32][33];
    const int n0 = blockIdx.x * 32, c0 = blockIdx.y * 32, bp = blockIdx.z;
    const int tx = threadIdx.x, ty = threadIdx.y;   // 32 x 8

    float mem[4] = {0.f, 0.f, 0.f, 0.f};

    #pragma unroll
    for (int t = 0; t < TT; ++t) {
        const int b = t * BP + bp;
        const float* ab = attn + (size_t)b * CN;
        __syncthreads();
        #pragma unroll
        for (int r = 0; r < 4; ++r) {
            int cl = ty * 4 + r;
            tile[cl][tx] = ab[(size_t)(c0 + cl) * NDIM + n0 + tx];
        }
        __syncthreads();
        __half* sb = st + ((size_t)b * NDIM + n0) * CDIM + c0;
        #pragma unroll
        for (int r = 0; r < 4; ++r) {
            int nl = ty * 4 + r;
            float m = mem[r] * 0.5f + tile[tx][nl];
            float sv = (m > 1.0f) ? 1.0f : 0.0f;
            if (sv != 0.0f) m = 0.f;
            mem[r] = m;
            sb[(size_t)nl * CDIM + tx] = __float2half_rn(sv);
        }
    }
}

// ---------------------------------------------------------------------------
// Proj GEMM + BN (shared-operand HMMA, NP=2), 128x256 tile.
// ---------------------------------------------------------------------------
__device__ __forceinline__ void proj_load_chunk(
    const __half* __restrict__ A0, const __half* __restrict__ A1,
    const __half* __restrict__ B0,
    int mBase, int n0g, int kOff, uint32_t buf, int tid)
{
    #pragma unroll
    for (int it = 0; it < 16; ++it) {
        int i = tid + it * 256;
        int s = i & 7;
        const __half* g;
        uint32_t dst;
        if (i < 1024)      { int r = i >> 3;          g = A0 + (size_t)(mBase + r) * CDIM + kOff + s * 8; dst = 0u     + swz((uint32_t)(r*128 + s*16)); }
        else if (i < 2048) { int r = (i - 1024) >> 3; g = A1 + (size_t)(mBase + r) * CDIM + kOff + s * 8; dst = 16384u + swz((uint32_t)(r*128 + s*16)); }
        else               { int r = (i - 2048) >> 3; g = B0 + (size_t)(n0g  + r) * CDIM + kOff + s * 8; dst = 32768u + swz((uint32_t)(r*128 + s*16)); }
        cp_async16(buf + dst, g);
    }
}

__global__ void __launch_bounds__(256, 1)
proj_gemm(const __half* __restrict__ A0g, const __half* __restrict__ A1g,
          const __half* __restrict__ B0g,
          float* __restrict__ Ybase,
          const float* __restrict__ bg, const float* __restrict__ bb,
          const float* __restrict__ bm, const float* __restrict__ bv)
{
    extern __shared__ __align__(128) unsigned char dsm[];
    const uint32_t sbase = smem_u32(dsm);
    const int tid = threadIdx.x, lane = tid & 31, wid = tid >> 5;
    const int warpM = wid >> 2, warpN = wid & 3;
    const int b = blockIdx.z;
    const int mBase = blockIdx.y * 128;
    const int n0g   = blockIdx.x * 256;

    const __half* B0 = B0g + (size_t)b * CN;

    float acc[4][8][4];
    #pragma unroll
    for (int i = 0; i < 4; ++i)
        #pragma unroll
        for (int j = 0; j < 8; ++j)
            #pragma unroll
            for (int k = 0; k < 4; ++k) acc[i][j][k] = 0.f;

    proj_load_chunk(A0g, A1g, B0, mBase, n0g, 0, sbase, tid);
    asm volatile("cp.async.commit_group;");

    int buf = 0;
    #pragma unroll 1
    for (int c = 0; c < 8; ++c) {
        if (c < 7) {
            proj_load_chunk(A0g, A1g, B0, mBase, n0g, (c + 1) * 64,
                            sbase + (buf ^ 1) * PBUF, tid);
            asm volatile("cp.async.commit_group;");
            asm volatile("cp.async.wait_group 1;");
        } else {
            asm volatile("cp.async.wait_group 0;");
        }
        __syncthreads();

        const uint32_t base = sbase + buf * PBUF;
        #pragma unroll
        for (int ks = 0; ks < 4; ++ks) {
            uint32_t a0[4][4], a1[4][4];
            const int khA = ks * 16 + (lane >> 4) * 8;
            #pragma unroll
            for (int mt = 0; mt < 4; ++mt) {
                int row = warpM * 64 + mt * 16 + (lane & 7) + ((lane >> 3) & 1) * 8;
                uint32_t bo = swz((uint32_t)(row * 128 + khA * 2));
                LDSM4(a0[mt][0], a0[mt][1], a0[mt][2], a0[mt][3], base + bo);
                LDSM4(a1[mt][0], a1[mt][1], a1[mt][2], a1[mt][3], base + 16384u + bo);
            }
            const int khB = ks * 16 + ((lane >> 3) & 1) * 8;
            #pragma unroll
            for (int nt2 = 0; nt2 < 4; ++nt2) {
                int nrow = warpN * 64 + nt2 * 16 + (lane & 7) + ((lane >> 4) & 1) * 8;
                uint32_t bo = swz((uint32_t)(nrow * 128 + khB * 2));
                uint32_t rb[4];
                LDSM4(rb[0], rb[1], rb[2], rb[3], base + 32768u + bo);
                #pragma unroll
                for (int mt = 0; mt < 4; ++mt) {
                    mma16816(acc[mt][nt2*2+0], a0[mt], rb[0], rb[1]);
                    mma16816(acc[mt][nt2*2+1], a0[mt], rb[2], rb[3]);
                    mma16816(acc[mt][nt2*2+0], a1[mt], rb[0], rb[1]);
                    mma16816(acc[mt][nt2*2+1], a1[mt], rb[2], rb[3]);
                }
            }
        }
        __syncthreads();
        buf ^= 1;
    }

    #pragma unroll
    for (int mt = 0; mt < 4; ++mt) {
        int o0 = mBase + warpM * 64 + mt * 16 + (lane >> 2);
        #pragma unroll
        for (int hf = 0; hf < 2; ++hf) {
            int o = o0 + hf * 8;
            int bnIdx = 3 * CDIM + o;
            float* rowP = Ybase + ((size_t)b * CDIM + o) * NDIM;
            float inv  = bg[bnIdx] / sqrtf(bv[bnIdx] + EPSF);
            float bias = bb[bnIdx] - bm[bnIdx] * inv;
            #pragma unroll
            for (int nt = 0; nt < 8; ++nt) {
                int nn = n0g + warpN * 64 + nt * 8 + (lane & 3) * 2;
                float2 v;
                v.x = acc[mt][nt][hf * 2 + 0] * inv + bias;
                v.y = acc[mt][nt][hf * 2 + 1] * inv + bias;
                *(float2*)(rowP + nn) = v;
            }
        }
    }
}

// ---------------------------------------------------------------------------
// launch
// ---------------------------------------------------------------------------
extern "C" void kernel_launch(void* const* d_in, const int* in_sizes, int n_in,
                              void* d_out, int out_size)
{
    (void)in_sizes; (void)n_in; (void)out_size;
    const float* x  = (const float*)d_in[0];
    const float* wq = (const float*)d_in[1];
    const float* wk = (const float*)d_in[2];
    const float* wv = (const float*)d_in[3];
    const float* wp = (const float*)d_in[4];
    const float* bg = (const float*)d_in[5];
    const float* bb = (const float*)d_in[6];
    const float* bm = (const float*)d_in[7];
    const float* bv = (const float*)d_in[8];
    float* out = (float*)d_out;

    cudaFuncSetAttribute(qkv_gemm_lif, cudaFuncAttributeMaxDynamicSharedMemorySize, QSMEM);
    cudaFuncSetAttribute(proj_gemm,    cudaFuncAttributeMaxDynamicSharedMemorySize, PSMEM);
    cudaFuncSetAttribute(attn_kernel,  cudaFuncAttributeMaxDynamicSharedMemorySize, ASMEM);

    unsigned char *spk;
    float* attn;
    __half *w2, *wp2, *xt2, *st;
    cudaGetSymbolAddress((void**)&spk,  g_spk);
    cudaGetSymbolAddress((void**)&attn, g_attn);
    cudaGetSymbolAddress((void**)&w2,   g_w2);
    cudaGetSymbolAddress((void**)&wp2,  g_wp2);
    cudaGetSymbolAddress((void**)&xt2,  g_xt2);
    cudaGetSymbolAddress((void**)&st,   g_st);

    // 1. splits
    wsplit_kernel<<<(MTOT_QKV*CDIM + 255)/256, 256>>>(wq, wk, wv, wp);
    xsplit_kernel<<<dim3(16,16,BDIM), dim3(32,8)>>>(x);

    // 2. fused qkv GEMM + BN + LIF -> spikes (u8)
    qkv_gemm_lif<<<dim3(NDIM/128, MTOT_QKV/128, BP), 256, QSMEM>>>(
        w2, w2 + (size_t)MTOT_QKV*CDIM, xt2, xt2 + (size_t)BDIM*CN,
        spk, bg, bb, bm, bv);

    // 3. spiking attention (HMMA, bit-exact) -> fp32 pre-acts
    attn_kernel<<<BDIM * HH, 256, ASMEM>>>(spk, attn);

    // 4. fused LIF + transpose -> fp16 spikes [b][n][c]
    lift_kernel<<<dim3(16, 16, BP), dim3(32, 8)>>>(attn, st);

    // 5. proj GEMM + BN -> out
    proj_gemm<<<dim3(NDIM/256, CDIM/128, BDIM), 256, PSMEM>>>(
        wp2, wp2 + (size_t)CDIM*CDIM, st, out, bg, bb, bm, bv);
}

// round 13
// speedup vs baseline: 2.1171x; 1.0244x over previous
#include <cuda_runtime.h>
#include <cuda_fp16.h>
#include <cstdint>
#include <cmath>

#define CDIM 512
#define NDIM 512
#define BDIM 64
#define TT 4
#define BP 16           // BDIM / TT
#define HH 8
#define GDIM 64
#define EPSF 1e-5f
#define CN (CDIM*NDIM)  // 262144
#define MTOT_QKV 1536

// qkv fused kernel smem: stage = A0(16K)+A1(16K)+B0(16K)+B1(16K) = 64KB
#define QBUF 65536
#define QSMEM (2*QBUF + 65536)    // + 64KB membrane state = 196608

// proj kernel smem (256-wide B)
#define PBUF 98304
#define PSMEM (2*PBUF)

// attn smem: kb(4K) + vb(4K) + MsT fp16(8K) + qf fp16 [64][512](64K)
#define ASMEM 81920

// ---------------------------------------------------------------------------
// Scratch (device globals: allocation-free per harness rules)
// ---------------------------------------------------------------------------
__device__ __half        g_w2  [2ull*MTOT_QKV*CDIM];          // qkv weight splits
__device__ __half        g_wp2 [2ull*CDIM*CDIM];              // proj weight splits
__device__ __half        g_xt2 [2ull*BDIM*CN];                // x splits, [s][b][n][c]
__device__ unsigned char g_spk [3ull*BDIM*CN];                // qkv spikes [w][b][c][n]
__device__ float         g_attn[(unsigned long long)BDIM*CN]; // attn out pre-LIF
__device__ __half        g_st  [(unsigned long long)BDIM*CN]; // final spikes fp16 [b][n][c]

// ---------------------------------------------------------------------------
// PTX helpers (baseline sm_80+, valid on compute_103 target)
// ---------------------------------------------------------------------------
__device__ __forceinline__ uint32_t smem_u32(const void* p) {
    uint32_t a;
    asm("{ .reg .u64 t; cvta.to.shared.u64 t, %1; cvt.u32.u64 %0, t; }" : "=r"(a) : "l"(p));
    return a;
}
#define LDSM4(r0,r1,r2,r3,addr) \
    asm volatile("ldmatrix.sync.aligned.m8n8.x4.shared.b16 {%0,%1,%2,%3}, [%4];" \
        : "=r"(r0),"=r"(r1),"=r"(r2),"=r"(r3) : "r"(addr))
#define LDSM4T(r0,r1,r2,r3,addr) \
    asm volatile("ldmatrix.sync.aligned.m8n8.x4.trans.shared.b16 {%0,%1,%2,%3}, [%4];" \
        : "=r"(r0),"=r"(r1),"=r"(r2),"=r"(r3) : "r"(addr))

__device__ __forceinline__ void mma16816(float* c, const uint32_t* a,
                                         uint32_t b0, uint32_t b1) {
    asm volatile("mma.sync.aligned.m16n8k16.row.col.f32.f16.f16.f32 "
        "{%0,%1,%2,%3}, {%4,%5,%6,%7}, {%8,%9}, {%0,%1,%2,%3};"
        : "+f"(c[0]), "+f"(c[1]), "+f"(c[2]), "+f"(c[3])
        : "r"(a[0]), "r"(a[1]), "r"(a[2]), "r"(a[3]), "r"(b0), "r"(b1));
}
__device__ __forceinline__ void cp_async16(uint32_t dst, const void* src) {
    asm volatile("cp.async.cg.shared.global [%0], [%1], 16;" :: "r"(dst), "l"(src));
}
__device__ __forceinline__ uint32_t swz(uint32_t bo) {
    return bo ^ (((bo >> 7) & 7u) << 4);
}
// pack 4 spike bytes (each 0/1) into bits 0..3
__device__ __forceinline__ uint32_t nib4(uint32_t v) {
    return ((v & 0x01010101u) * 0x10204080u) >> 28;
}

// ---------------------------------------------------------------------------
// Weight splits: w -> (fp16 hi, fp16 residual)
// ---------------------------------------------------------------------------
__global__ void wsplit_kernel(const float* __restrict__ wq, const float* __restrict__ wk,
                              const float* __restrict__ wv, const float* __restrict__ wp)
{
    int i = blockIdx.x * 256 + threadIdx.x;
    if (i < MTOT_QKV * CDIM) {
        int o = i >> 9;
        const float* src = (o < 512) ? wq : (o < 1024 ? wk : wv);
        float v = src[((o & 511) << 9) | (i & 511)];
        __half h0 = __float2half_rn(v);
        float r1 = v - __half2float(h0);
        g_w2[i] = h0;
        g_w2[(size_t)MTOT_QKV * CDIM + i] = __float2half_rn(r1);
    }
    if (i < CDIM * CDIM) {
        float v = wp[i];
        __half h0 = __float2half_rn(v);
        float r1 = v - __half2float(h0);
        g_wp2[i] = h0;
        g_wp2[(size_t)CDIM * CDIM + i] = __float2half_rn(r1);
    }
}

// ---------------------------------------------------------------------------
// x split + transpose: x[b][c][n] fp32 -> g_xt2[s][b][n][c] fp16 (2 splits)
// ---------------------------------------------------------------------------
__global__ void xsplit_kernel(const float* __restrict__ x)
{
    __shared__ float tile[32][33];
    const int b = blockIdx.z, c0 = blockIdx.y * 32, n0 = blockIdx.x * 32;
    const float* xb = x + (size_t)b * CN;
    const int tx = threadIdx.x, ty = threadIdx.y;   // 32 x 8
    #pragma unroll
    for (int r = 0; r < 4; ++r) {
        int cl = ty * 4 + r;
        tile[cl][tx] = xb[(size_t)(c0 + cl) * NDIM + n0 + tx];
    }
    __syncthreads();
    const size_t SEG = (size_t)BDIM * CN;
    #pragma unroll
    for (int r = 0; r < 4; ++r) {
        int nl = ty * 4 + r, cl = tx;
        float v = tile[cl][nl];
        __half h0 = __float2half_rn(v);
        float r1 = v - __half2float(h0);
        size_t o = ((size_t)b * NDIM + (n0 + nl)) * CDIM + c0 + cl;
        g_xt2[o] = h0;
        g_xt2[SEG + o] = __float2half_rn(r1);
    }
}

// ---------------------------------------------------------------------------
// Fused QKV: split-HMMA GEMM + BN + LIF scan over T, spikes out (u8).
// CTA: 128(M) x 128(N), grid.z = b' (16); inner loop t=0..3, b = t*16+b'.
// ---------------------------------------------------------------------------
__device__ __forceinline__ void qkv_load_chunk(
    const __half* __restrict__ A0, const __half* __restrict__ A1,
    const __half* __restrict__ B0, const __half* __restrict__ B1,
    int mBase, int n0g, int kOff, uint32_t buf, int tid)
{
    #pragma unroll
    for (int it = 0; it < 16; ++it) {
        int i = tid + it * 256;          // 0..4095
        int s = i & 7;
        int r = (i >> 3) & 127;
        int seg = i >> 10;               // 0:A0 1:A1 2:B0 3:B1
        const __half* g;
        if (seg == 0)      g = A0 + (size_t)(mBase + r) * CDIM + kOff + s * 8;
        else if (seg == 1) g = A1 + (size_t)(mBase + r) * CDIM + kOff + s * 8;
        else if (seg == 2) g = B0 + (size_t)(n0g  + r) * CDIM + kOff + s * 8;
        else               g = B1 + (size_t)(n0g  + r) * CDIM + kOff + s * 8;
        cp_async16(buf + (uint32_t)(seg << 14) + swz((uint32_t)(r * 128 + s * 16)), g);
    }
}

__global__ void __launch_bounds__(256, 1)
qkv_gemm_lif(const __half* __restrict__ A0g, const __half* __restrict__ A1g,
             const __half* __restrict__ B0base, const __half* __restrict__ B1base,
             unsigned char* __restrict__ spk,
             const float* __restrict__ bg, const float* __restrict__ bb,
             const float* __restrict__ bm, const float* __restrict__ bv)
{
    extern __shared__ __align__(128) unsigned char dsm[];
    const uint32_t sbase = smem_u32(dsm);
    float* memS = (float*)(dsm + 2 * QBUF);

    const int tid = threadIdx.x, lane = tid & 31, wid = tid >> 5;
    const int warpM = wid >> 2, warpN = wid & 3;       // 2 x 4 warps, 64x32 each
    const int bz    = blockIdx.z;                      // b' 0..15
    const int mBase = blockIdx.y * 128;
    const int n0g   = blockIdx.x * 128;

    float invR[4][2], biasR[4][2];
    size_t rowB[4][2];
    #pragma unroll
    for (int mt = 0; mt < 4; ++mt)
        #pragma unroll
        for (int hf = 0; hf < 2; ++hf) {
            int o = mBase + warpM * 64 + mt * 16 + (lane >> 2) + hf * 8;
            int w = o >> 9, c = o & 511;
            float inv = bg[w * CDIM + c] / sqrtf(bv[w * CDIM + c] + EPSF);
            invR[mt][hf]  = inv;
            biasR[mt][hf] = bb[w * CDIM + c] - bm[w * CDIM + c] * inv;
            rowB[mt][hf]  = (size_t)w * BDIM * CN + (size_t)c * NDIM;
        }

    #pragma unroll
    for (int idx = 0; idx < 64; ++idx) memS[idx * 256 + tid] = 0.f;

    float acc[4][4][4];
    #pragma unroll
    for (int i = 0; i < 4; ++i)
        #pragma unroll
        for (int j = 0; j < 4; ++j)
            #pragma unroll
            for (int k = 0; k < 4; ++k) acc[i][j][k] = 0.f;

    #pragma unroll 1
    for (int t = 0; t < TT; ++t) {
        const int b = t * BP + bz;
        const __half* B0 = B0base + (size_t)b * CN;
        const __half* B1 = B1base + (size_t)b * CN;

        qkv_load_chunk(A0g, A1g, B0, B1, mBase, n0g, 0, sbase, tid);
        asm volatile("cp.async.commit_group;");

        int buf = 0;
        #pragma unroll 1
        for (int c = 0; c < 8; ++c) {
            if (c < 7) {
                qkv_load_chunk(A0g, A1g, B0, B1, mBase, n0g, (c + 1) * 64,
                               sbase + (buf ^ 1) * QBUF, tid);
                asm volatile("cp.async.commit_group;");
                asm volatile("cp.async.wait_group 1;");
            } else {
                asm volatile("cp.async.wait_group 0;");
            }
            __syncthreads();

            const uint32_t base = sbase + buf * QBUF;
            #pragma unroll
            for (int ks = 0; ks < 4; ++ks) {
                uint32_t a0[4][4], a1[4][4];
                const int khA = ks * 16 + (lane >> 4) * 8;
                #pragma unroll
                for (int mt = 0; mt < 4; ++mt) {
                    int row = warpM * 64 + mt * 16 + (lane & 7) + ((lane >> 3) & 1) * 8;
                    uint32_t bo = swz((uint32_t)(row * 128 + khA * 2));
                    LDSM4(a0[mt][0], a0[mt][1], a0[mt][2], a0[mt][3], base + bo);
                    LDSM4(a1[mt][0], a1[mt][1], a1[mt][2], a1[mt][3], base + 16384u + bo);
                }
                const int khB = ks * 16 + ((lane >> 3) & 1) * 8;
                #pragma unroll
                for (int nt2 = 0; nt2 < 2; ++nt2) {
                    int nrow = warpN * 32 + nt2 * 16 + (lane & 7) + ((lane >> 4) & 1) * 8;
                    uint32_t bo = swz((uint32_t)(nrow * 128 + khB * 2));
                    uint32_t rb[4];
                    LDSM4(rb[0], rb[1], rb[2], rb[3], base + 32768u + bo);
                    #pragma unroll
                    for (int mt = 0; mt < 4; ++mt) {
                        mma16816(acc[mt][nt2*2+0], a0[mt], rb[0], rb[1]);
                        mma16816(acc[mt][nt2*2+1], a0[mt], rb[2], rb[3]);
                        mma16816(acc[mt][nt2*2+0], a1[mt], rb[0], rb[1]);
                        mma16816(acc[mt][nt2*2+1], a1[mt], rb[2], rb[3]);
                    }
                    LDSM4(rb[0], rb[1], rb[2], rb[3], base + 49152u + bo);
                    #pragma unroll
                    for (int mt = 0; mt < 4; ++mt) {
                        mma16816(acc[mt][nt2*2+0], a0[mt], rb[0], rb[1]);
                        mma16816(acc[mt][nt2*2+1], a0[mt], rb[2], rb[3]);
                    }
                }
            }
            __syncthreads();
            buf ^= 1;
        }

        // epilogue: BN + LIF step + spike write (per-thread-exclusive memS)
        #pragma unroll
        for (int mt = 0; mt < 4; ++mt)
            #pragma unroll
            for (int hf = 0; hf < 2; ++hf) {
                const float inv = invR[mt][hf], bias = biasR[mt][hf];
                unsigned char* ucRow = spk + rowB[mt][hf] + (size_t)b * CN;
                #pragma unroll
                for (int nt = 0; nt < 4; ++nt) {
                    int idx = mt * 16 + nt * 4 + hf * 2;
                    int nn  = n0g + warpN * 32 + nt * 8 + (lane & 3) * 2;
                    float pre0 = acc[mt][nt][hf*2+0] * inv + bias;
                    float pre1 = acc[mt][nt][hf*2+1] * inv + bias;
                    float m0 = memS[(idx+0) * 256 + tid] * 0.5f + pre0;
                    float m1 = memS[(idx+1) * 256 + tid] * 0.5f + pre1;
                    uchar2 s;
                    s.x = m0 > 1.0f; if (s.x) m0 = 0.f;
                    s.y = m1 > 1.0f; if (s.y) m1 = 0.f;
                    memS[(idx+0) * 256 + tid] = m0;
                    memS[(idx+1) * 256 + tid] = m1;
                    *(uchar2*)(ucRow + nn) = s;
                    acc[mt][nt][hf*2+0] = 0.f;
                    acc[mt][nt][hf*2+1] = 0.f;
                }
            }
    }
}

// ---------------------------------------------------------------------------
// Spiking attention via HMMA (exact): out[d][n] = sum_e MsT[d][e] * q[e][n].
// Phase A bitpack is ballot-free: each thread builds whole 32-bit words with
// the 0x10204080 multiply trick (identical bits, ~5x fewer ops).
// ---------------------------------------------------------------------------
__global__ void __launch_bounds__(256)
attn_kernel(const unsigned char* __restrict__ spk,
            float* __restrict__ attn)
{
    extern __shared__ __align__(128) unsigned char asmem[];
    unsigned int (*kb)[16] = (unsigned int (*)[16])(asmem);
    unsigned int (*vb)[16] = (unsigned int (*)[16])(asmem + 4096);
    const uint32_t msBase = smem_u32(asmem) + 8192;   // MsT fp16 [64][64], 128B rows, swz
    const uint32_t qfBase = smem_u32(asmem) + 16384;  // qf  fp16 [64][512], 1024B rows, XOR sw
    char* msPtr = (char*)asmem + 8192;
    char* qfPtr = (char*)asmem + 16384;

    const int bh = blockIdx.x;
    const int b  = bh / HH;
    const int h  = bh % HH;
    const size_t head_off = ((size_t)b * CDIM + (size_t)h * GDIM) * NDIM;
    const unsigned char* qS = spk + 0ull * BDIM * CN + head_off;
    const unsigned char* kS = spk + 1ull * BDIM * CN + head_off;
    const unsigned char* vS = spk + 2ull * BDIM * CN + head_off;

    const int tid  = threadIdx.x;
    const int lane = tid & 31;
    const int warp = tid >> 5;

    // Phase A1: ballot-free bitpack of k and v (1024 words each)
    #pragma unroll
    for (int it = 0; it < 8; ++it) {
        int i = tid + it * 256;          // 0..2047
        int e = (i >> 4) & 63;
        int w = i & 15;
        const unsigned char* src = (i < 1024) ? kS : vS;
        const uint4* p = (const uint4*)(src + (size_t)e * NDIM + w * 32);
        uint4 va = p[0], vbv = p[1];
        uint32_t word =  nib4(va.x)        | (nib4(va.y)  << 4)
                      | (nib4(va.z)  << 8) | (nib4(va.w)  << 12)
                      | (nib4(vbv.x) << 16)| (nib4(vbv.y) << 20)
                      | (nib4(vbv.z) << 24)| (nib4(vbv.w) << 28);
        if (i < 1024) kb[e][w] = word; else vb[e][w] = word;
    }

    // Phase A2: convert q u8 -> fp16 slab
    #pragma unroll
    for (int it = 0; it < 32; ++it) {    // 8192 u32 = 64 x 512 bytes
        int i  = tid + it * 256;
        int e  = i >> 7;
        int n4 = (i & 127) * 4;
        unsigned int q4 = *(const unsigned int*)(qS + (size_t)e * NDIM + n4);
        __half2 h01 = __floats2half2_rn((float)( q4        & 255u),
                                        (float)((q4 >>  8) & 255u));
        __half2 h23 = __floats2half2_rn((float)((q4 >> 16) & 255u),
                                        (float)( q4 >> 24));
        uint32_t bo = ((uint32_t)(n4 * 2)) ^ (((uint32_t)e & 7u) << 4);
        char* p = qfPtr + (size_t)e * 1024 + bo;
        *(__half2*)(p)     = h01;
        *(__half2*)(p + 4) = h23;
    }
    __syncthreads();

    // Phase B: popcount M, store transposed fp16 (exact): MsT[d][e]
    {
        int e  = tid >> 2;
        int d0 = (tid & 3) * 16;
        unsigned int kr[16];
        #pragma unroll
        for (int w = 0; w < 16; ++w) kr[w] = kb[e][w];
        #pragma unroll
        for (int dd = 0; dd < 16; ++dd) {
            int d = d0 + dd;
            int s = 0;
            #pragma unroll
            for (int w = 0; w < 16; ++w) s += __popc(kr[w] & vb[d][w]);
            *(__half*)(msPtr + swz((uint32_t)(d * 128 + e * 2))) =
                __float2half_rn((float)s * 0.125f);
        }
    }
    __syncthreads();

    // Phase C: HMMA.  M=64(d) x N=64(n per warp) x K=64(e).
    float acc[4][8][4];
    #pragma unroll
    for (int i = 0; i < 4; ++i)
        #pragma unroll
        for (int j = 0; j < 8; ++j)
            #pragma unroll
            for (int k = 0; k < 4; ++k) acc[i][j][k] = 0.f;

    const int nWarp = warp * 64;
    #pragma unroll
    for (int ks = 0; ks < 4; ++ks) {
        uint32_t af[4][4];
        const int khA = ks * 16 + (lane >> 4) * 8;
        #pragma unroll
        for (int mt = 0; mt < 4; ++mt) {
            int row = mt * 16 + (lane & 7) + ((lane >> 3) & 1) * 8;
            LDSM4(af[mt][0], af[mt][1], af[mt][2], af[mt][3],
                  msBase + swz((uint32_t)(row * 128 + khA * 2)));
        }
        #pragma unroll
        for (int nt = 0; nt < 4; ++nt) {
            int eRow = ks * 16 + ((lane >> 3) & 1) * 8 + (lane & 7);
            int nCol = nWarp + nt * 16 + ((lane >> 4) & 1) * 8;
            uint32_t bo = ((uint32_t)(nCol * 2)) ^ (((uint32_t)eRow & 7u) << 4);
            uint32_t rb[4];
            LDSM4T(rb[0], rb[1], rb[2], rb[3],
                   qfBase + (uint32_t)(eRow * 1024) + bo);
            #pragma unroll
            for (int mt = 0; mt < 4; ++mt) {
                mma16816(acc[mt][nt*2+0], af[mt], rb[0], rb[1]);
                mma16816(acc[mt][nt*2+1], af[mt], rb[2], rb[3]);
            }
        }
    }

    // epilogue: write out[d][n]
    float* outp = attn + head_off;
    #pragma unroll
    for (int mt = 0; mt < 4; ++mt) {
        int dr0 = mt * 16 + (lane >> 2);
        #pragma unroll
        for (int nt8 = 0; nt8 < 8; ++nt8) {
            int n0 = nWarp + nt8 * 8 + (lane & 3) * 2;
            *(float2*)(outp + (size_t)dr0       * NDIM + n0) =
                make_float2(acc[mt][nt8][0], acc[mt][nt8][1]);
            *(float2*)(outp + (size_t)(dr0 + 8) * NDIM + n0) =
                make_float2(acc[mt][nt8][2], acc[mt][nt8][3]);
        }
    }
}

// ---------------------------------------------------------------------------
// Fused LIF + transpose: attn fp32 [b][c][n] -> spikes fp16 [b][n][c].
// ---------------------------------------------------------------------------
__global__ void lift_kernel(const float* __restrict__ attn, __half* __restrict__ st)
{
    __shared__ float tile[32][33];
    const int n0 = blockIdx.x * 32, c0 = blockIdx.y * 32, bp = blockIdx.z;
    const int tx = threadIdx.x, ty = threadIdx.y;   // 32 x 8

    float mem[4] = {0.f, 0.f, 0.f, 0.f};

    #pragma unroll
    for (int t = 0; t < TT; ++t) {
        const int b = t * BP + bp;
        const float* ab = attn + (size_t)b * CN;
        __syncthreads();
        #pragma unroll
        for (int r = 0; r < 4; ++r) {
            int cl = ty * 4 + r;
            tile[cl][tx] = ab[(size_t)(c0 + cl) * NDIM + n0 + tx];
        }
        __syncthreads();
        __half* sb = st + ((size_t)b * NDIM + n0) * CDIM + c0;
        #pragma unroll
        for (int r = 0; r < 4; ++r) {
            int nl = ty * 4 + r;
            float m = mem[r] * 0.5f + tile[tx][nl];
            float sv = (m > 1.0f) ? 1.0f : 0.0f;
            if (sv != 0.0f) m = 0.f;
            mem[r] = m;
            sb[(size_t)nl * CDIM + tx] = __float2half_rn(sv);
        }
    }
}

// ---------------------------------------------------------------------------
// Proj GEMM + BN (shared-operand HMMA, NP=2), 128x256 tile.
// ---------------------------------------------------------------------------
__device__ __forceinline__ void proj_load_chunk(
    const __half* __restrict__ A0, const __half* __restrict__ A1,
    const __half* __restrict__ B0,
    int mBase, int n0g, int kOff, uint32_t buf, int tid)
{
    #pragma unroll
    for (int it = 0; it < 16; ++it) {
        int i = tid + it * 256;
        int s = i & 7;
        const __half* g;
        uint32_t dst;
        if (i < 1024)      { int r = i >> 3;          g = A0 + (size_t)(mBase + r) * CDIM + kOff + s * 8; dst = 0u     + swz((uint32_t)(r*128 + s*16)); }
        else if (i < 2048) { int r = (i - 1024) >> 3; g = A1 + (size_t)(mBase + r) * CDIM + kOff + s * 8; dst = 16384u + swz((uint32_t)(r*128 + s*16)); }
        else               { int r = (i - 2048) >> 3; g = B0 + (size_t)(n0g  + r) * CDIM + kOff + s * 8; dst = 32768u + swz((uint32_t)(r*128 + s*16)); }
        cp_async16(buf + dst, g);
    }
}

__global__ void __launch_bounds__(256, 1)
proj_gemm(const __half* __restrict__ A0g, const __half* __restrict__ A1g,
          const __half* __restrict__ B0g,
          float* __restrict__ Ybase,
          const float* __restrict__ bg, const float* __restrict__ bb,
          const float* __restrict__ bm, const float* __restrict__ bv)
{
    extern __shared__ __align__(128) unsigned char dsm[];
    const uint32_t sbase = smem_u32(dsm);
    const int tid = threadIdx.x, lane = tid & 31, wid = tid >> 5;
    const int warpM = wid >> 2, warpN = wid & 3;
    const int b = blockIdx.z;
    const int mBase = blockIdx.y * 128;
    const int n0g   = blockIdx.x * 256;

    const __half* B0 = B0g + (size_t)b * CN;

    float acc[4][8][4];
    #pragma unroll
    for (int i = 0; i < 4; ++i)
        #pragma unroll
        for (int j = 0; j < 8; ++j)
            #pragma unroll
            for (int k = 0; k < 4; ++k) acc[i][j][k] = 0.f;

    proj_load_chunk(A0g, A1g, B0, mBase, n0g, 0, sbase, tid);
    asm volatile("cp.async.commit_group;");

    int buf = 0;
    #pragma unroll 1
    for (int c = 0; c < 8; ++c) {
        if (c < 7) {
            proj_load_chunk(A0g, A1g, B0, mBase, n0g, (c + 1) * 64,
                            sbase + (buf ^ 1) * PBUF, tid);
            asm volatile("cp.async.commit_group;");
            asm volatile("cp.async.wait_group 1;");
        } else {
            asm volatile("cp.async.wait_group 0;");
        }
        __syncthreads();

        const uint32_t base = sbase + buf * PBUF;
        #pragma unroll
        for (int ks = 0; ks < 4; ++ks) {
            uint32_t a0[4][4], a1[4][4];
            const int khA = ks * 16 + (lane >> 4) * 8;
            #pragma unroll
            for (int mt = 0; mt < 4; ++mt) {
                int row = warpM * 64 + mt * 16 + (lane & 7) + ((lane >> 3) & 1) * 8;
                uint32_t bo = swz((uint32_t)(row * 128 + khA * 2));
                LDSM4(a0[mt][0], a0[mt][1], a0[mt][2], a0[mt][3], base + bo);
                LDSM4(a1[mt][0], a1[mt][1], a1[mt][2], a1[mt][3], base + 16384u + bo);
            }
            const int khB = ks * 16 + ((lane >> 3) & 1) * 8;
            #pragma unroll
            for (int nt2 = 0; nt2 < 4; ++nt2) {
                int nrow = warpN * 64 + nt2 * 16 + (lane & 7) + ((lane >> 4) & 1) * 8;
                uint32_t bo = swz((uint32_t)(nrow * 128 + khB * 2));
                uint32_t rb[4];
                LDSM4(rb[0], rb[1], rb[2], rb[3], base + 32768u + bo);
                #pragma unroll
                for (int mt = 0; mt < 4; ++mt) {
                    mma16816(acc[mt][nt2*2+0], a0[mt], rb[0], rb[1]);
                    mma16816(acc[mt][nt2*2+1], a0[mt], rb[2], rb[3]);
                    mma16816(acc[mt][nt2*2+0], a1[mt], rb[0], rb[1]);
                    mma16816(acc[mt][nt2*2+1], a1[mt], rb[2], rb[3]);
                }
            }
        }
        __syncthreads();
        buf ^= 1;
    }

    #pragma unroll
    for (int mt = 0; mt < 4; ++mt) {
        int o0 = mBase + warpM * 64 + mt * 16 + (lane >> 2);
        #pragma unroll
        for (int hf = 0; hf < 2; ++hf) {
            int o = o0 + hf * 8;
            int bnIdx = 3 * CDIM + o;
            float* rowP = Ybase + ((size_t)b * CDIM + o) * NDIM;
            float inv  = bg[bnIdx] / sqrtf(bv[bnIdx] + EPSF);
            float bias = bb[bnIdx] - bm[bnIdx] * inv;
            #pragma unroll
            for (int nt = 0; nt < 8; ++nt) {
                int nn = n0g + warpN * 64 + nt * 8 + (lane & 3) * 2;
                float2 v;
                v.x = acc[mt][nt][hf * 2 + 0] * inv + bias;
                v.y = acc[mt][nt][hf * 2 + 1] * inv + bias;
                *(float2*)(rowP + nn) = v;
            }
        }
    }
}

// ---------------------------------------------------------------------------
// launch
// ---------------------------------------------------------------------------
extern "C" void kernel_launch(void* const* d_in, const int* in_sizes, int n_in,
                              void* d_out, int out_size)
{
    (void)in_sizes; (void)n_in; (void)out_size;
    const float* x  = (const float*)d_in[0];
    const float* wq = (const float*)d_in[1];
    const float* wk = (const float*)d_in[2];
    const float* wv = (const float*)d_in[3];
    const float* wp = (const float*)d_in[4];
    const float* bg = (const float*)d_in[5];
    const float* bb = (const float*)d_in[6];
    const float* bm = (const float*)d_in[7];
    const float* bv = (const float*)d_in[8];
    float* out = (float*)d_out;

    cudaFuncSetAttribute(qkv_gemm_lif, cudaFuncAttributeMaxDynamicSharedMemorySize, QSMEM);
    cudaFuncSetAttribute(proj_gemm,    cudaFuncAttributeMaxDynamicSharedMemorySize, PSMEM);
    cudaFuncSetAttribute(attn_kernel,  cudaFuncAttributeMaxDynamicSharedMemorySize, ASMEM);

    unsigned char *spk;
    float* attn;
    __half *w2, *wp2, *xt2, *st;
    cudaGetSymbolAddress((void**)&spk,  g_spk);
    cudaGetSymbolAddress((void**)&attn, g_attn);
    cudaGetSymbolAddress((void**)&w2,   g_w2);
    cudaGetSymbolAddress((void**)&wp2,  g_wp2);
    cudaGetSymbolAddress((void**)&xt2,  g_xt2);
    cudaGetSymbolAddress((void**)&st,   g_st);

    // 1. splits
    wsplit_kernel<<<(MTOT_QKV*CDIM + 255)/256, 256>>>(wq, wk, wv, wp);
    xsplit_kernel<<<dim3(16,16,BDIM), dim3(32,8)>>>(x);

    // 2. fused qkv GEMM + BN + LIF -> spikes (u8)
    qkv_gemm_lif<<<dim3(NDIM/128, MTOT_QKV/128, BP), 256, QSMEM>>>(
        w2, w2 + (size_t)MTOT_QKV*CDIM, xt2, xt2 + (size_t)BDIM*CN,
        spk, bg, bb, bm, bv);

    // 3. spiking attention (HMMA, bit-exact, ballot-free bitpack)
    attn_kernel<<<BDIM * HH, 256, ASMEM>>>(spk, attn);

    // 4. fused LIF + transpose -> fp16 spikes [b][n][c]
    lift_kernel<<<dim3(16, 16, BP), dim3(32, 8)>>>(attn, st);

    // 5. proj GEMM + BN -> out
    proj_gemm<<<dim3(NDIM/256, CDIM/128, BDIM), 256, PSMEM>>>(
        wp2, wp2 + (size_t)CDIM*CDIM, st, out, bg, bb, bm, bv);
}